// round 1
// baseline (speedup 1.0000x reference)
#include <cuda_runtime.h>
#include <cuda_bf16.h>
#include <math.h>

// Problem constants
#define BATCH 4
#define SEQ   1024
#define HID   1024
#define NHEAD 16
#define DHEAD 64
#define FFDIM 4096
#define ROWS  (BATCH * SEQ)        // 4096

// ---------------------------------------------------------------------------
// Scratch (device globals; allocation-free per harness rules)
// ---------------------------------------------------------------------------
__device__ float g_y1 [ROWS * HID];
__device__ float g_y2 [ROWS * HID];
__device__ float g_q  [ROWS * HID];
__device__ float g_k  [ROWS * HID];
__device__ float g_v  [ROWS * HID];
__device__ float g_o  [ROWS * HID];
__device__ float g_x  [ROWS * HID];
__device__ float g_xln[ROWS * HID];
__device__ float g_ffh[ROWS * FFDIM];

// ---------------------------------------------------------------------------
// LayerNorm: one block per row of 1024, 256 threads, float4 per thread
// ---------------------------------------------------------------------------
__global__ __launch_bounds__(256)
void ln_kernel(const float* __restrict__ x, const float* __restrict__ g,
               const float* __restrict__ b, float* __restrict__ y)
{
    int row = blockIdx.x;
    int t   = threadIdx.x;
    const float4* xr = (const float4*)(x + (size_t)row * HID);
    float4 v = xr[t];
    float s  = v.x + v.y + v.z + v.w;
    float ss = fmaf(v.x, v.x, fmaf(v.y, v.y, fmaf(v.z, v.z, v.w * v.w)));

    #pragma unroll
    for (int o2 = 16; o2; o2 >>= 1) {
        s  += __shfl_xor_sync(0xffffffffu, s,  o2);
        ss += __shfl_xor_sync(0xffffffffu, ss, o2);
    }
    __shared__ float rs[8], rss[8];
    __shared__ float sh_mean, sh_rstd;
    int w = t >> 5, l = t & 31;
    if (l == 0) { rs[w] = s; rss[w] = ss; }
    __syncthreads();
    if (t == 0) {
        float S = 0.f, SS = 0.f;
        #pragma unroll
        for (int i = 0; i < 8; i++) { S += rs[i]; SS += rss[i]; }
        float mean = S * (1.f / HID);
        float var  = SS * (1.f / HID) - mean * mean;
        sh_mean = mean;
        sh_rstd = rsqrtf(var + 1e-5f);
    }
    __syncthreads();
    float mean = sh_mean, rstd = sh_rstd;
    float4 gv = ((const float4*)g)[t];
    float4 bv = ((const float4*)b)[t];
    float4 r;
    r.x = (v.x - mean) * rstd * gv.x + bv.x;
    r.y = (v.y - mean) * rstd * gv.y + bv.y;
    r.z = (v.z - mean) * rstd * gv.z + bv.z;
    r.w = (v.w - mean) * rstd * gv.w + bv.w;
    ((float4*)(y + (size_t)row * HID))[t] = r;
}

// ---------------------------------------------------------------------------
// SGEMM: C[M,N] = A[M,K] @ B[K,N], row-major, fused epilogues.
// 128x128 tile, BK=8, 256 threads, 8x8 per-thread microtile.
// ---------------------------------------------------------------------------
#define BM 128
#define BN 128
#define BKK 8

enum { EP_BIAS = 0, EP_SCALE = 1, EP_RES = 2, EP_GELU = 3 };

__device__ __forceinline__ float gelu_exact(float v)
{
    return 0.5f * v * (1.0f + erff(v * 0.70710678118654752f));
}

__global__ __launch_bounds__(256)
void sgemm_kernel(const float* __restrict__ A, const float* __restrict__ B,
                  const float* __restrict__ bias, const float* __restrict__ res,
                  float* __restrict__ C, int M, int N, int K,
                  int mode, float scale)
{
    __shared__ float As[BKK][BM];
    __shared__ float Bs[BKK][BN];

    int tid = threadIdx.x;
    int tr  = tid >> 4;          // 0..15
    int tc  = tid & 15;          // 0..15
    int row0 = blockIdx.y * BM;
    int col0 = blockIdx.x * BN;

    int aRow = tid >> 1;                 // 0..127
    int aCol = (tid & 1) * 4;            // 0 or 4
    int bRow = tid >> 5;                 // 0..7
    int bCol = (tid & 31) * 4;           // 0..124

    const float* Ag = A + (size_t)(row0 + aRow) * K + aCol;
    const float* Bg = B + (size_t)bRow * N + col0 + bCol;

    float acc[8][8] = {};

    for (int kt = 0; kt < K; kt += BKK) {
        float4 av = *(const float4*)Ag;  Ag += BKK;
        float4 bv = *(const float4*)Bg;  Bg += (size_t)BKK * N;

        As[aCol + 0][aRow] = av.x;
        As[aCol + 1][aRow] = av.y;
        As[aCol + 2][aRow] = av.z;
        As[aCol + 3][aRow] = av.w;
        *(float4*)&Bs[bRow][bCol] = bv;
        __syncthreads();

        #pragma unroll
        for (int k = 0; k < BKK; k++) {
            float ar[8], br[8];
            *(float4*)&ar[0] = *(const float4*)&As[k][tr * 8];
            *(float4*)&ar[4] = *(const float4*)&As[k][tr * 8 + 4];
            *(float4*)&br[0] = *(const float4*)&Bs[k][tc * 8];
            *(float4*)&br[4] = *(const float4*)&Bs[k][tc * 8 + 4];
            #pragma unroll
            for (int i = 0; i < 8; i++)
                #pragma unroll
                for (int j = 0; j < 8; j++)
                    acc[i][j] += ar[i] * br[j];
        }
        __syncthreads();
    }

    // Epilogue
    float bcol[8];
    #pragma unroll
    for (int j = 0; j < 8; j++) bcol[j] = bias[col0 + tc * 8 + j];

    #pragma unroll
    for (int i = 0; i < 8; i++) {
        int r = row0 + tr * 8 + i;
        size_t base = (size_t)r * N + col0 + tc * 8;
        float vj[8];
        #pragma unroll
        for (int j = 0; j < 8; j++) vj[j] = acc[i][j] + bcol[j];

        if (mode == EP_SCALE) {
            #pragma unroll
            for (int j = 0; j < 8; j++) vj[j] *= scale;
        } else if (mode == EP_RES) {
            #pragma unroll
            for (int j = 0; j < 8; j++) vj[j] += res[base + j];
        } else if (mode == EP_GELU) {
            #pragma unroll
            for (int j = 0; j < 8; j++) vj[j] = gelu_exact(vj[j]);
        }
        *(float4*)&C[base]     = make_float4(vj[0], vj[1], vj[2], vj[3]);
        *(float4*)&C[base + 4] = make_float4(vj[4], vj[5], vj[6], vj[7]);
    }
}

// ---------------------------------------------------------------------------
// Flash attention: grid (B*NH, S/BR), 256 threads.
// Q/K/V stored row-major [B*S, H], head slice at column h*64.
// Online softmax over 16 kv tiles of 64; bias streamed from global.
// ---------------------------------------------------------------------------
#define BR 64
#define BC 64
#define SPAD 65   // degree-2 bank conflicts at worst

#define FLASH_SMEM_FLOATS (4 * BR * SPAD + 3 * BR)
#define FLASH_SMEM_BYTES  (FLASH_SMEM_FLOATS * 4)

__global__ __launch_bounds__(256)
void flash_kernel(const float* __restrict__ Q, const float* __restrict__ Kg,
                  const float* __restrict__ Vg, const float* __restrict__ bias,
                  float* __restrict__ O)
{
    extern __shared__ float sm[];
    float* Qs  = sm;
    float* Ks  = Qs + BR * SPAD;
    float* Vs  = Ks + BC * SPAD;
    float* Ss  = Vs + BC * SPAD;
    float* m_s = Ss + BR * SPAD;
    float* l_s = m_s + BR;
    float* f_s = l_s + BR;

    int bh = blockIdx.x;                 // 0..63
    int b  = bh >> 4;
    int h  = bh & 15;
    int q0 = blockIdx.y * BR;
    int tid = threadIdx.x;
    int tr = tid >> 4, tc = tid & 15;

    // Load Q tile (64 x 64)
    const float* Qbase = Q + ((size_t)(b * SEQ + q0)) * HID + h * DHEAD;
    #pragma unroll
    for (int e = tid; e < BR * 16; e += 256) {
        int r = e >> 4, c4 = (e & 15) * 4;
        float4 v = *(const float4*)(Qbase + (size_t)r * HID + c4);
        Qs[r * SPAD + c4 + 0] = v.x;
        Qs[r * SPAD + c4 + 1] = v.y;
        Qs[r * SPAD + c4 + 2] = v.z;
        Qs[r * SPAD + c4 + 3] = v.w;
    }
    if (tid < BR) { m_s[tid] = -1e30f; l_s[tid] = 0.f; }

    float o_acc[4][4] = {};
    __syncthreads();

    const float* biasBase = bias + ((size_t)bh * SEQ + q0) * SEQ;

    for (int k0 = 0; k0 < SEQ; k0 += BC) {
        // Load K, V tiles
        const float* Kbase = Kg + ((size_t)(b * SEQ + k0)) * HID + h * DHEAD;
        const float* Vbase = Vg + ((size_t)(b * SEQ + k0)) * HID + h * DHEAD;
        #pragma unroll
        for (int e = tid; e < BC * 16; e += 256) {
            int r = e >> 4, c4 = (e & 15) * 4;
            float4 kv = *(const float4*)(Kbase + (size_t)r * HID + c4);
            Ks[r * SPAD + c4 + 0] = kv.x;
            Ks[r * SPAD + c4 + 1] = kv.y;
            Ks[r * SPAD + c4 + 2] = kv.z;
            Ks[r * SPAD + c4 + 3] = kv.w;
            float4 vv = *(const float4*)(Vbase + (size_t)r * HID + c4);
            Vs[r * SPAD + c4 + 0] = vv.x;
            Vs[r * SPAD + c4 + 1] = vv.y;
            Vs[r * SPAD + c4 + 2] = vv.z;
            Vs[r * SPAD + c4 + 3] = vv.w;
        }
        __syncthreads();

        // S = Q @ K^T  (thread computes 4x4)
        float s_acc[4][4] = {};
        #pragma unroll 8
        for (int d = 0; d < DHEAD; d++) {
            float a0 = Qs[(tr * 4 + 0) * SPAD + d];
            float a1 = Qs[(tr * 4 + 1) * SPAD + d];
            float a2 = Qs[(tr * 4 + 2) * SPAD + d];
            float a3 = Qs[(tr * 4 + 3) * SPAD + d];
            float b0 = Ks[(tc * 4 + 0) * SPAD + d];
            float b1 = Ks[(tc * 4 + 1) * SPAD + d];
            float b2 = Ks[(tc * 4 + 2) * SPAD + d];
            float b3 = Ks[(tc * 4 + 3) * SPAD + d];
            s_acc[0][0] += a0 * b0; s_acc[0][1] += a0 * b1; s_acc[0][2] += a0 * b2; s_acc[0][3] += a0 * b3;
            s_acc[1][0] += a1 * b0; s_acc[1][1] += a1 * b1; s_acc[1][2] += a1 * b2; s_acc[1][3] += a1 * b3;
            s_acc[2][0] += a2 * b0; s_acc[2][1] += a2 * b1; s_acc[2][2] += a2 * b2; s_acc[2][3] += a2 * b3;
            s_acc[3][0] += a3 * b0; s_acc[3][1] += a3 * b1; s_acc[3][2] += a3 * b2; s_acc[3][3] += a3 * b3;
        }
        // Add bias, store to Ss
        #pragma unroll
        for (int i = 0; i < 4; i++) {
            int qr = tr * 4 + i;
            const float* brow = biasBase + (size_t)qr * SEQ + k0 + tc * 4;
            #pragma unroll
            for (int j = 0; j < 4; j++)
                Ss[qr * SPAD + tc * 4 + j] = s_acc[i][j] + brow[j];
        }
        __syncthreads();

        // Online softmax: 4 threads per row, 16 cols each
        {
            int row  = tid >> 2;
            int part = tid & 3;
            float* srow = Ss + row * SPAD + part * 16;
            float m_old = m_s[row];
            float mx = -1e30f;
            #pragma unroll
            for (int c = 0; c < 16; c++) mx = fmaxf(mx, srow[c]);
            mx = fmaxf(mx, __shfl_xor_sync(0xffffffffu, mx, 1));
            mx = fmaxf(mx, __shfl_xor_sync(0xffffffffu, mx, 2));
            float m_new = fmaxf(m_old, mx);
            float f = __expf(m_old - m_new);
            float lsum = 0.f;
            #pragma unroll
            for (int c = 0; c < 16; c++) {
                float p = __expf(srow[c] - m_new);
                srow[c] = p;
                lsum += p;
            }
            lsum += __shfl_xor_sync(0xffffffffu, lsum, 1);
            lsum += __shfl_xor_sync(0xffffffffu, lsum, 2);
            if (part == 0) {
                m_s[row] = m_new;
                l_s[row] = l_s[row] * f + lsum;
                f_s[row] = f;
            }
        }
        __syncthreads();

        // Rescale accumulators, accumulate P @ V
        float fr[4];
        #pragma unroll
        for (int i = 0; i < 4; i++) fr[i] = f_s[tr * 4 + i];
        #pragma unroll
        for (int i = 0; i < 4; i++)
            #pragma unroll
            for (int d = 0; d < 4; d++)
                o_acc[i][d] *= fr[i];

        #pragma unroll 8
        for (int j = 0; j < BC; j++) {
            float p0 = Ss[(tr * 4 + 0) * SPAD + j];
            float p1 = Ss[(tr * 4 + 1) * SPAD + j];
            float p2 = Ss[(tr * 4 + 2) * SPAD + j];
            float p3 = Ss[(tr * 4 + 3) * SPAD + j];
            float v0 = Vs[j * SPAD + tc * 4 + 0];
            float v1 = Vs[j * SPAD + tc * 4 + 1];
            float v2 = Vs[j * SPAD + tc * 4 + 2];
            float v3 = Vs[j * SPAD + tc * 4 + 3];
            o_acc[0][0] += p0 * v0; o_acc[0][1] += p0 * v1; o_acc[0][2] += p0 * v2; o_acc[0][3] += p0 * v3;
            o_acc[1][0] += p1 * v0; o_acc[1][1] += p1 * v1; o_acc[1][2] += p1 * v2; o_acc[1][3] += p1 * v3;
            o_acc[2][0] += p2 * v0; o_acc[2][1] += p2 * v1; o_acc[2][2] += p2 * v2; o_acc[2][3] += p2 * v3;
            o_acc[3][0] += p3 * v0; o_acc[3][1] += p3 * v1; o_acc[3][2] += p3 * v2; o_acc[3][3] += p3 * v3;
        }
        __syncthreads();
    }

    // Epilogue: normalize and store
    #pragma unroll
    for (int i = 0; i < 4; i++) {
        int qr = tr * 4 + i;
        float inv = 1.f / l_s[qr];
        float* orow = O + ((size_t)(b * SEQ + q0 + qr)) * HID + h * DHEAD + tc * 4;
        orow[0] = o_acc[i][0] * inv;
        orow[1] = o_acc[i][1] * inv;
        orow[2] = o_acc[i][2] * inv;
        orow[3] = o_acc[i][3] * inv;
    }
}

// ---------------------------------------------------------------------------
// Launch
// ---------------------------------------------------------------------------
extern "C" void kernel_launch(void* const* d_in, const int* in_sizes, int n_in,
                              void* d_out, int out_size)
{
    const float* x1        = (const float*)d_in[0];
    const float* x2        = (const float*)d_in[1];
    const float* attn_bias = (const float*)d_in[2];
    const float* ln1_g = (const float*)d_in[3];
    const float* ln1_b = (const float*)d_in[4];
    const float* ln2_g = (const float*)d_in[5];
    const float* ln2_b = (const float*)d_in[6];
    const float* wq = (const float*)d_in[7];
    const float* bq = (const float*)d_in[8];
    const float* wk = (const float*)d_in[9];
    const float* bk = (const float*)d_in[10];
    const float* wv = (const float*)d_in[11];
    const float* bv = (const float*)d_in[12];
    const float* wo = (const float*)d_in[13];
    const float* bo = (const float*)d_in[14];
    const float* lnf_g = (const float*)d_in[15];
    const float* lnf_b = (const float*)d_in[16];
    const float* w1 = (const float*)d_in[17];
    const float* b1 = (const float*)d_in[18];
    const float* w2 = (const float*)d_in[19];
    const float* b2 = (const float*)d_in[20];
    float* out = (float*)d_out;

    float *y1, *y2, *q, *k, *v, *o, *x, *xln, *ffh;
    cudaGetSymbolAddress((void**)&y1,  g_y1);
    cudaGetSymbolAddress((void**)&y2,  g_y2);
    cudaGetSymbolAddress((void**)&q,   g_q);
    cudaGetSymbolAddress((void**)&k,   g_k);
    cudaGetSymbolAddress((void**)&v,   g_v);
    cudaGetSymbolAddress((void**)&o,   g_o);
    cudaGetSymbolAddress((void**)&x,   g_x);
    cudaGetSymbolAddress((void**)&xln, g_xln);
    cudaGetSymbolAddress((void**)&ffh, g_ffh);

    // 1. LayerNorms of the two inputs
    ln_kernel<<<ROWS, 256>>>(x1, ln1_g, ln1_b, y1);
    ln_kernel<<<ROWS, 256>>>(x2, ln2_g, ln2_b, y2);

    // 2. Q, K, V projections (q gets *= D^-0.5)
    dim3 gQKV(HID / BN, ROWS / BM);  // (8, 32)
    sgemm_kernel<<<gQKV, 256>>>(y2, wq, bq, nullptr, q, ROWS, HID, HID, EP_SCALE, 0.125f);
    sgemm_kernel<<<gQKV, 256>>>(y1, wk, bk, nullptr, k, ROWS, HID, HID, EP_BIAS, 1.f);
    sgemm_kernel<<<gQKV, 256>>>(y1, wv, bv, nullptr, v, ROWS, HID, HID, EP_BIAS, 1.f);

    // 3. Flash attention
    cudaFuncSetAttribute(flash_kernel, cudaFuncAttributeMaxDynamicSharedMemorySize,
                         FLASH_SMEM_BYTES);
    flash_kernel<<<dim3(BATCH * NHEAD, SEQ / BR), 256, FLASH_SMEM_BYTES>>>(
        q, k, v, attn_bias, o);

    // 4. Output projection + residual (x = x2 + attn_out)
    sgemm_kernel<<<gQKV, 256>>>(o, wo, bo, x2, x, ROWS, HID, HID, EP_RES, 1.f);

    // 5. Final LayerNorm
    ln_kernel<<<ROWS, 256>>>(x, lnf_g, lnf_b, xln);

    // 6. FFN1 + exact GELU
    dim3 gFF1(FFDIM / BN, ROWS / BM);  // (32, 32)
    sgemm_kernel<<<gFF1, 256>>>(xln, w1, b1, nullptr, ffh, ROWS, FFDIM, HID, EP_GELU, 1.f);

    // 7. FFN2 + residual (out = x + ffn_out)
    dim3 gFF2(HID / BN, ROWS / BM);    // (8, 32)
    sgemm_kernel<<<gFF2, 256>>>(ffh, w2, b2, x, out, ROWS, HID, FFDIM, EP_RES, 1.f);
}

// round 5
// speedup vs baseline: 2.7620x; 2.7620x over previous
#include <cuda_runtime.h>
#include <cuda_bf16.h>
#include <math.h>
#include <stdint.h>

#define BATCH 4
#define SEQ   1024
#define HID   1024
#define DHEAD 64
#define FFDIM 4096
#define ROWS  (BATCH * SEQ)

// scratch
__device__ float g_q[ROWS * HID];
__device__ float g_k[ROWS * HID];
__device__ float g_v[ROWS * HID];
__device__ float g_x[ROWS * HID];
__device__ __nv_bfloat16 g_y1h[ROWS * HID], g_y1l[ROWS * HID];
__device__ __nv_bfloat16 g_y2h[ROWS * HID], g_y2l[ROWS * HID];
__device__ __nv_bfloat16 g_oh [ROWS * HID], g_ol [ROWS * HID];
__device__ __nv_bfloat16 g_xlh[ROWS * HID], g_xll[ROWS * HID];
__device__ __nv_bfloat16 g_fh [ROWS * FFDIM], g_fl[ROWS * FFDIM];
__device__ __nv_bfloat16 g_wqh[HID * HID], g_wql[HID * HID];
__device__ __nv_bfloat16 g_wkh[HID * HID], g_wkl[HID * HID];
__device__ __nv_bfloat16 g_wvh[HID * HID], g_wvl[HID * HID];
__device__ __nv_bfloat16 g_woh[HID * HID], g_wol[HID * HID];
__device__ __nv_bfloat16 g_w1h[HID * FFDIM], g_w1l[HID * FFDIM];
__device__ __nv_bfloat16 g_w2h[FFDIM * HID], g_w2l[FFDIM * HID];

// ---------------- helpers ----------------
__device__ __forceinline__ uint32_t smem_u32(const void* p) {
    uint32_t a;
    asm("{ .reg .u64 t; cvta.to.shared.u64 t, %1; cvt.u32.u64 %0, t; }" : "=r"(a) : "l"(p));
    return a;
}
#define CP_ASYNC16(dst, src) \
    asm volatile("cp.async.cg.shared.global [%0], [%1], 16;" :: "r"(dst), "l"(src) : "memory")
#define CP_COMMIT() asm volatile("cp.async.commit_group;" ::: "memory")
#define CP_WAIT1()  asm volatile("cp.async.wait_group 1;" ::: "memory")
#define CP_WAIT0()  asm volatile("cp.async.wait_group 0;" ::: "memory")

#define LDX4(r, a) \
    asm volatile("ldmatrix.sync.aligned.m8n8.x4.shared.b16 {%0,%1,%2,%3}, [%4];" \
        : "=r"((r)[0]), "=r"((r)[1]), "=r"((r)[2]), "=r"((r)[3]) : "r"(a))
#define LDX4T(r, a) \
    asm volatile("ldmatrix.sync.aligned.m8n8.x4.trans.shared.b16 {%0,%1,%2,%3}, [%4];" \
        : "=r"((r)[0]), "=r"((r)[1]), "=r"((r)[2]), "=r"((r)[3]) : "r"(a))

__device__ __forceinline__ void mma_bf16(float* d, const uint32_t* a, const uint32_t* b) {
    asm volatile(
        "mma.sync.aligned.m16n8k16.row.col.f32.bf16.bf16.f32 "
        "{%0,%1,%2,%3}, {%4,%5,%6,%7}, {%8,%9}, {%0,%1,%2,%3};"
        : "+f"(d[0]), "+f"(d[1]), "+f"(d[2]), "+f"(d[3])
        : "r"(a[0]), "r"(a[1]), "r"(a[2]), "r"(a[3]), "r"(b[0]), "r"(b[1]));
}

// split 8 floats into hi/lo bf16x2 packs
__device__ __forceinline__ void splitpack(const float* v, uint4& H, uint4& L) {
    uint32_t h[4], l[4];
    #pragma unroll
    for (int p = 0; p < 4; p++) {
        __nv_bfloat16 h0 = __float2bfloat16(v[2*p]), h1 = __float2bfloat16(v[2*p+1]);
        float r0 = v[2*p] - __bfloat162float(h0), r1 = v[2*p+1] - __bfloat162float(h1);
        __nv_bfloat16 l0 = __float2bfloat16(r0), l1 = __float2bfloat16(r1);
        h[p] = ((uint32_t)__bfloat16_as_ushort(h1) << 16) | __bfloat16_as_ushort(h0);
        l[p] = ((uint32_t)__bfloat16_as_ushort(l1) << 16) | __bfloat16_as_ushort(l0);
    }
    H = make_uint4(h[0], h[1], h[2], h[3]);
    L = make_uint4(l[0], l[1], l[2], l[3]);
}
__device__ __forceinline__ uint32_t split1(float v, float& rem) {
    __nv_bfloat16 h = __float2bfloat16(v);
    rem = v - __bfloat162float(h);
    return (uint32_t)__bfloat16_as_ushort(h);
}
__device__ __forceinline__ float gelu_exact(float v) {
    return 0.5f * v * (1.0f + erff(v * 0.70710678118654752f));
}

// ---------------- weight split (elementwise, layout preserved [K,N]) --------
__global__ __launch_bounds__(256)
void wsplit(const float* __restrict__ w, __nv_bfloat16* __restrict__ h,
            __nv_bfloat16* __restrict__ l, int n)
{
    int i = (blockIdx.x * 256 + threadIdx.x) * 8;
    if (i >= n) return;
    float v[8];
    *(float4*)&v[0] = *(const float4*)(w + i);
    *(float4*)&v[4] = *(const float4*)(w + i + 4);
    uint4 H, L; splitpack(v, H, L);
    *(uint4*)(h + i) = H;
    *(uint4*)(l + i) = L;
}

// ---------------- LayerNorm -> bf16 hi/lo ----------------
__global__ __launch_bounds__(128)
void ln_split(const float* __restrict__ x, const float* __restrict__ g,
              const float* __restrict__ b, __nv_bfloat16* __restrict__ yh,
              __nv_bfloat16* __restrict__ yl)
{
    int row = blockIdx.x, t = threadIdx.x;
    const float4* xr = (const float4*)(x + (size_t)row * HID);
    float4 a0 = xr[t * 2], a1 = xr[t * 2 + 1];
    float s  = a0.x + a0.y + a0.z + a0.w + a1.x + a1.y + a1.z + a1.w;
    float ss = a0.x*a0.x + a0.y*a0.y + a0.z*a0.z + a0.w*a0.w
             + a1.x*a1.x + a1.y*a1.y + a1.z*a1.z + a1.w*a1.w;
    #pragma unroll
    for (int o2 = 16; o2; o2 >>= 1) {
        s  += __shfl_xor_sync(0xffffffffu, s,  o2);
        ss += __shfl_xor_sync(0xffffffffu, ss, o2);
    }
    __shared__ float rs[4], rss[4];
    __shared__ float smean, srstd;
    int w = t >> 5;
    if ((t & 31) == 0) { rs[w] = s; rss[w] = ss; }
    __syncthreads();
    if (t == 0) {
        float S = rs[0]+rs[1]+rs[2]+rs[3], SS = rss[0]+rss[1]+rss[2]+rss[3];
        float mean = S * (1.f / HID);
        smean = mean;
        srstd = rsqrtf(SS * (1.f / HID) - mean * mean + 1e-5f);
    }
    __syncthreads();
    float mean = smean, rstd = srstd;
    const float4* gp = (const float4*)g; const float4* bp = (const float4*)b;
    float4 g0 = gp[t*2], g1 = gp[t*2+1], b0 = bp[t*2], b1 = bp[t*2+1];
    float v[8];
    v[0]=(a0.x-mean)*rstd*g0.x+b0.x; v[1]=(a0.y-mean)*rstd*g0.y+b0.y;
    v[2]=(a0.z-mean)*rstd*g0.z+b0.z; v[3]=(a0.w-mean)*rstd*g0.w+b0.w;
    v[4]=(a1.x-mean)*rstd*g1.x+b1.x; v[5]=(a1.y-mean)*rstd*g1.y+b1.y;
    v[6]=(a1.z-mean)*rstd*g1.z+b1.z; v[7]=(a1.w-mean)*rstd*g1.w+b1.w;
    uint4 H, L; splitpack(v, H, L);
    ((uint4*)yh)[(size_t)row * 128 + t] = H;
    ((uint4*)yl)[(size_t)row * 128 + t] = L;
}

// ---------------- mma.sync GEMM: C = A[M,K] @ B[K,N], split-bf16 ------------
// CTA 128x128, 8 warps (4M x 2N), warp 32x64, K-chunk 64, 2-stage cp.async.
// smem per stage: Ah[128][64], Al, Bh[64][128], Bl (bf16) = 64KB; 2 stages.
#define STAGE_B 65536
#define GEMM_DSM (2 * STAGE_B)
enum { M_F32 = 0, M_RES = 1, M_GELU = 2 };

__global__ __launch_bounds__(256)
void mma_gemm(const __nv_bfloat16* __restrict__ Ah, const __nv_bfloat16* __restrict__ Al,
              const __nv_bfloat16* __restrict__ Bh, const __nv_bfloat16* __restrict__ Bl,
              const float* __restrict__ bias, const float* __restrict__ res,
              float* __restrict__ outF, __nv_bfloat16* __restrict__ outH,
              __nv_bfloat16* __restrict__ outL, int M, int N, int K,
              int mode, float scale)
{
    extern __shared__ __align__(1024) char dsm[];
    const uint32_t base = smem_u32(dsm);
    int tid = threadIdx.x;
    int m0 = blockIdx.y * 128, n0 = blockIdx.x * 128;
    int nch = K >> 6;

    // -------- producer addressing (per-thread granule assignments) --------
    // A: 128 rows x 8 granules x2(hi/lo); B: 64 rows x 16 granules x2.
    int arow = tid >> 1;               // with i-loop: rows tid>>1 + i*... see below
    // issue one stage of cp.async
    auto issue = [&](int c, int st) {
        uint32_t sb = base + st * STAGE_B;
        // A tiles: 1024 granules each for hi/lo; 256 threads -> 4 each
        #pragma unroll
        for (int i = 0; i < 4; i++) {
            int idx = tid + i * 256;
            int r = idx >> 3, g = idx & 7;
            const __nv_bfloat16* sh = Ah + (size_t)(m0 + r) * K + c * 64 + g * 8;
            const __nv_bfloat16* sl = Al + (size_t)(m0 + r) * K + c * 64 + g * 8;
            uint32_t d = sb + r * 128 + ((g ^ (r & 7)) << 4);
            CP_ASYNC16(d, sh);
            CP_ASYNC16(d + 16384, sl);
        }
        // B tiles: 64 rows x 16 granules
        #pragma unroll
        for (int i = 0; i < 4; i++) {
            int idx = tid + i * 256;
            int r = idx >> 4, g = idx & 15;
            const __nv_bfloat16* sh = Bh + (size_t)(c * 64 + r) * N + n0 + g * 8;
            const __nv_bfloat16* sl = Bl + (size_t)(c * 64 + r) * N + n0 + g * 8;
            uint32_t pg = (g & 8) | ((g ^ (r & 7)) & 7);
            uint32_t d = sb + 32768 + r * 256 + (pg << 4);
            CP_ASYNC16(d, sh);
            CP_ASYNC16(d + 16384, sl);
        }
        CP_COMMIT();
    };

    // -------- consumer per-thread constants --------
    int w = tid >> 5, t = tid & 31;
    int mrow_loc = (w & 3) * 32;        // warp M offset in CTA tile
    int ncol_loc = (w >> 2) * 64;       // warp N offset
    int gt = t >> 4;                    // ldmatrix: granule half (0/1)
    int rl = ((t >> 3) & 1) * 8 + (t & 7); // row-within-16 for ldmatrix
    int xa = rl & 7;

    float acc[2][8][4] = {};

    issue(0, 0);
    if (nch > 1) issue(1, 1);

    for (int c = 0; c < nch; c++) {
        if (c + 1 < nch) { CP_WAIT1(); } else { CP_WAIT0(); }
        __syncthreads();
        uint32_t sb = base + (c & 1) * STAGE_B;
        uint32_t aB = sb + (mrow_loc + rl) * 128;
        uint32_t bB = sb + 32768 + rl * 256;
        #pragma unroll
        for (int s = 0; s < 4; s++) {
            uint32_t Ahf[2][4], Alf[2][4];
            #pragma unroll
            for (int mt = 0; mt < 2; mt++) {
                uint32_t ad = aB + mt * 2048 + (((s * 2 + gt) ^ xa) << 4);
                LDX4(Ahf[mt], ad);
                LDX4(Alf[mt], ad + 16384);
            }
            #pragma unroll
            for (int ni = 0; ni < 4; ni++) {
                int g = (ncol_loc >> 4) * 2 + ni * 2 + gt;
                uint32_t pg = (g & 8) | ((g ^ xa) & 7);
                uint32_t bd = bB + s * 4096 + (pg << 4);
                uint32_t Bhf[4], Blf[4];
                LDX4T(Bhf, bd);
                LDX4T(Blf, bd + 16384);
                #pragma unroll
                for (int mt = 0; mt < 2; mt++) {
                    #pragma unroll
                    for (int nj = 0; nj < 2; nj++) {
                        float* d = acc[mt][ni * 2 + nj];
                        mma_bf16(d, Ahf[mt], Bhf + nj * 2);
                        mma_bf16(d, Ahf[mt], Blf + nj * 2);
                        mma_bf16(d, Alf[mt], Bhf + nj * 2);
                    }
                }
            }
        }
        __syncthreads();
        if (c + 2 < nch) issue(c + 2, c & 1);
    }

    // -------- epilogue --------
    int qr = t >> 2, qc = t & 3;
    #pragma unroll
    for (int mt = 0; mt < 2; mt++) {
        #pragma unroll
        for (int nf = 0; nf < 8; nf++) {
            int col = n0 + ncol_loc + nf * 8 + qc * 2;
            float2 bv = *(const float2*)(bias + col);
            #pragma unroll
            for (int half = 0; half < 2; half++) {
                int row = m0 + mrow_loc + mt * 16 + qr + half * 8;
                float v0 = acc[mt][nf][half * 2 + 0] + bv.x;
                float v1 = acc[mt][nf][half * 2 + 1] + bv.y;
                size_t off = (size_t)row * N + col;
                if (mode == M_GELU) {
                    float a0 = gelu_exact(v0), a1 = gelu_exact(v1);
                    float r0, r1;
                    uint32_t h0 = split1(a0, r0), h1 = split1(a1, r1);
                    __nv_bfloat16 l0 = __float2bfloat16(r0), l1 = __float2bfloat16(r1);
                    *(uint32_t*)(outH + off) = (h1 << 16) | h0;
                    *(uint32_t*)(outL + off) =
                        ((uint32_t)__bfloat16_as_ushort(l1) << 16) | __bfloat16_as_ushort(l0);
                } else {
                    v0 *= scale; v1 *= scale;
                    if (mode == M_RES) {
                        float2 rv = *(const float2*)(res + off);
                        v0 += rv.x; v1 += rv.y;
                    }
                    *(float2*)(outF + off) = make_float2(v0, v1);
                }
            }
        }
    }
}

// ---------------- Flash attention (SIMT; epilogue -> plain bf16 hi/lo) ------
#define BR 64
#define BC 64
#define SPAD 65
#define FLASH_SMEM_BYTES ((4 * BR * SPAD + 3 * BR) * 4)

__global__ __launch_bounds__(256)
void flash_kernel(const float* __restrict__ Q, const float* __restrict__ Kg,
                  const float* __restrict__ Vg, const float* __restrict__ bias,
                  __nv_bfloat16* __restrict__ Oh, __nv_bfloat16* __restrict__ Ol)
{
    extern __shared__ float sm[];
    float* Qs  = sm;
    float* Ks  = Qs + BR * SPAD;
    float* Vs  = Ks + BC * SPAD;
    float* Ss  = Vs + BC * SPAD;
    float* m_s = Ss + BR * SPAD;
    float* l_s = m_s + BR;
    float* f_s = l_s + BR;

    int bh = blockIdx.x, b = bh >> 4, h = bh & 15;
    int q0 = blockIdx.y * BR;
    int tid = threadIdx.x, tr = tid >> 4, tc = tid & 15;

    const float* Qbase = Q + ((size_t)(b * SEQ + q0)) * HID + h * DHEAD;
    #pragma unroll
    for (int e = tid; e < BR * 16; e += 256) {
        int r = e >> 4, c4 = (e & 15) * 4;
        float4 v = *(const float4*)(Qbase + (size_t)r * HID + c4);
        Qs[r*SPAD+c4] = v.x; Qs[r*SPAD+c4+1] = v.y; Qs[r*SPAD+c4+2] = v.z; Qs[r*SPAD+c4+3] = v.w;
    }
    if (tid < BR) { m_s[tid] = -1e30f; l_s[tid] = 0.f; }
    float o_acc[4][4] = {};
    __syncthreads();

    const float* biasBase = bias + ((size_t)bh * SEQ + q0) * SEQ;

    for (int k0 = 0; k0 < SEQ; k0 += BC) {
        const float* Kb = Kg + ((size_t)(b * SEQ + k0)) * HID + h * DHEAD;
        const float* Vb = Vg + ((size_t)(b * SEQ + k0)) * HID + h * DHEAD;
        #pragma unroll
        for (int e = tid; e < BC * 16; e += 256) {
            int r = e >> 4, c4 = (e & 15) * 4;
            float4 kv = *(const float4*)(Kb + (size_t)r * HID + c4);
            Ks[r*SPAD+c4] = kv.x; Ks[r*SPAD+c4+1] = kv.y; Ks[r*SPAD+c4+2] = kv.z; Ks[r*SPAD+c4+3] = kv.w;
            float4 vv = *(const float4*)(Vb + (size_t)r * HID + c4);
            Vs[r*SPAD+c4] = vv.x; Vs[r*SPAD+c4+1] = vv.y; Vs[r*SPAD+c4+2] = vv.z; Vs[r*SPAD+c4+3] = vv.w;
        }
        __syncthreads();

        float s_acc[4][4] = {};
        #pragma unroll 8
        for (int d = 0; d < DHEAD; d++) {
            float a0 = Qs[(tr*4+0)*SPAD+d], a1 = Qs[(tr*4+1)*SPAD+d];
            float a2 = Qs[(tr*4+2)*SPAD+d], a3 = Qs[(tr*4+3)*SPAD+d];
            float b0 = Ks[(tc*4+0)*SPAD+d], b1 = Ks[(tc*4+1)*SPAD+d];
            float b2 = Ks[(tc*4+2)*SPAD+d], b3 = Ks[(tc*4+3)*SPAD+d];
            s_acc[0][0]+=a0*b0; s_acc[0][1]+=a0*b1; s_acc[0][2]+=a0*b2; s_acc[0][3]+=a0*b3;
            s_acc[1][0]+=a1*b0; s_acc[1][1]+=a1*b1; s_acc[1][2]+=a1*b2; s_acc[1][3]+=a1*b3;
            s_acc[2][0]+=a2*b0; s_acc[2][1]+=a2*b1; s_acc[2][2]+=a2*b2; s_acc[2][3]+=a2*b3;
            s_acc[3][0]+=a3*b0; s_acc[3][1]+=a3*b1; s_acc[3][2]+=a3*b2; s_acc[3][3]+=a3*b3;
        }
        #pragma unroll
        for (int i = 0; i < 4; i++) {
            int qr = tr * 4 + i;
            const float* brow = biasBase + (size_t)qr * SEQ + k0 + tc * 4;
            #pragma unroll
            for (int j = 0; j < 4; j++)
                Ss[qr * SPAD + tc * 4 + j] = s_acc[i][j] + brow[j];
        }
        __syncthreads();
        {
            int row = tid >> 2, part = tid & 3;
            float* srow = Ss + row * SPAD + part * 16;
            float m_old = m_s[row];
            float mx = -1e30f;
            #pragma unroll
            for (int c = 0; c < 16; c++) mx = fmaxf(mx, srow[c]);
            mx = fmaxf(mx, __shfl_xor_sync(0xffffffffu, mx, 1));
            mx = fmaxf(mx, __shfl_xor_sync(0xffffffffu, mx, 2));
            float m_new = fmaxf(m_old, mx);
            float f = __expf(m_old - m_new);
            float lsum = 0.f;
            #pragma unroll
            for (int c = 0; c < 16; c++) {
                float p = __expf(srow[c] - m_new);
                srow[c] = p; lsum += p;
            }
            lsum += __shfl_xor_sync(0xffffffffu, lsum, 1);
            lsum += __shfl_xor_sync(0xffffffffu, lsum, 2);
            if (part == 0) { m_s[row] = m_new; l_s[row] = l_s[row] * f + lsum; f_s[row] = f; }
        }
        __syncthreads();

        float fr[4];
        #pragma unroll
        for (int i = 0; i < 4; i++) fr[i] = f_s[tr * 4 + i];
        #pragma unroll
        for (int i = 0; i < 4; i++)
            #pragma unroll
            for (int d = 0; d < 4; d++) o_acc[i][d] *= fr[i];

        #pragma unroll 8
        for (int j = 0; j < BC; j++) {
            float p0 = Ss[(tr*4+0)*SPAD+j], p1 = Ss[(tr*4+1)*SPAD+j];
            float p2 = Ss[(tr*4+2)*SPAD+j], p3 = Ss[(tr*4+3)*SPAD+j];
            float v0 = Vs[j*SPAD+tc*4], v1 = Vs[j*SPAD+tc*4+1];
            float v2 = Vs[j*SPAD+tc*4+2], v3 = Vs[j*SPAD+tc*4+3];
            o_acc[0][0]+=p0*v0; o_acc[0][1]+=p0*v1; o_acc[0][2]+=p0*v2; o_acc[0][3]+=p0*v3;
            o_acc[1][0]+=p1*v0; o_acc[1][1]+=p1*v1; o_acc[1][2]+=p1*v2; o_acc[1][3]+=p1*v3;
            o_acc[2][0]+=p2*v0; o_acc[2][1]+=p2*v1; o_acc[2][2]+=p2*v2; o_acc[2][3]+=p2*v3;
            o_acc[3][0]+=p3*v0; o_acc[3][1]+=p3*v1; o_acc[3][2]+=p3*v2; o_acc[3][3]+=p3*v3;
        }
        __syncthreads();
    }

    #pragma unroll
    for (int i = 0; i < 4; i++) {
        int qr = tr * 4 + i;
        float inv = 1.f / l_s[qr];
        #pragma unroll
        for (int j = 0; j < 4; j++) Qs[qr * SPAD + tc * 4 + j] = o_acc[i][j] * inv;
    }
    __syncthreads();
    #pragma unroll
    for (int e = tid; e < 512; e += 256) {
        int r = e >> 3, gl = e & 7;
        float v[8];
        #pragma unroll
        for (int j = 0; j < 8; j++) v[j] = Qs[r * SPAD + gl * 8 + j];
        uint4 H, L; splitpack(v, H, L);
        size_t m = (size_t)(b * SEQ + q0 + r);
        ((uint4*)Oh)[m * 128 + h * 8 + gl] = H;
        ((uint4*)Ol)[m * 128 + h * 8 + gl] = L;
    }
}

// ---------------- launch ----------------
extern "C" void kernel_launch(void* const* d_in, const int* in_sizes, int n_in,
                              void* d_out, int out_size)
{
    const float* x1 = (const float*)d_in[0];
    const float* x2 = (const float*)d_in[1];
    const float* attn_bias = (const float*)d_in[2];
    const float* ln1_g = (const float*)d_in[3];
    const float* ln1_b = (const float*)d_in[4];
    const float* ln2_g = (const float*)d_in[5];
    const float* ln2_b = (const float*)d_in[6];
    const float* wq = (const float*)d_in[7];
    const float* bq = (const float*)d_in[8];
    const float* wk = (const float*)d_in[9];
    const float* bk = (const float*)d_in[10];
    const float* wv = (const float*)d_in[11];
    const float* bv = (const float*)d_in[12];
    const float* wo = (const float*)d_in[13];
    const float* bo = (const float*)d_in[14];
    const float* lnf_g = (const float*)d_in[15];
    const float* lnf_b = (const float*)d_in[16];
    const float* w1 = (const float*)d_in[17];
    const float* b1 = (const float*)d_in[18];
    const float* w2 = (const float*)d_in[19];
    const float* b2 = (const float*)d_in[20];
    float* out = (float*)d_out;

    float *q, *k, *v, *x;
    __nv_bfloat16 *y1h,*y1l,*y2h,*y2l,*oh,*ol,*xlh,*xll,*fh,*fl;
    __nv_bfloat16 *wqh,*wql,*wkh,*wkl,*wvh,*wvl,*woh,*wol,*w1h,*w1l,*w2h,*w2l;
    cudaGetSymbolAddress((void**)&q, g_q);  cudaGetSymbolAddress((void**)&k, g_k);
    cudaGetSymbolAddress((void**)&v, g_v);  cudaGetSymbolAddress((void**)&x, g_x);
    cudaGetSymbolAddress((void**)&y1h, g_y1h); cudaGetSymbolAddress((void**)&y1l, g_y1l);
    cudaGetSymbolAddress((void**)&y2h, g_y2h); cudaGetSymbolAddress((void**)&y2l, g_y2l);
    cudaGetSymbolAddress((void**)&oh, g_oh);   cudaGetSymbolAddress((void**)&ol, g_ol);
    cudaGetSymbolAddress((void**)&xlh, g_xlh); cudaGetSymbolAddress((void**)&xll, g_xll);
    cudaGetSymbolAddress((void**)&fh, g_fh);   cudaGetSymbolAddress((void**)&fl, g_fl);
    cudaGetSymbolAddress((void**)&wqh, g_wqh); cudaGetSymbolAddress((void**)&wql, g_wql);
    cudaGetSymbolAddress((void**)&wkh, g_wkh); cudaGetSymbolAddress((void**)&wkl, g_wkl);
    cudaGetSymbolAddress((void**)&wvh, g_wvh); cudaGetSymbolAddress((void**)&wvl, g_wvl);
    cudaGetSymbolAddress((void**)&woh, g_woh); cudaGetSymbolAddress((void**)&wol, g_wol);
    cudaGetSymbolAddress((void**)&w1h, g_w1h); cudaGetSymbolAddress((void**)&w1l, g_w1l);
    cudaGetSymbolAddress((void**)&w2h, g_w2h); cudaGetSymbolAddress((void**)&w2l, g_w2l);

    cudaFuncSetAttribute(mma_gemm, cudaFuncAttributeMaxDynamicSharedMemorySize, GEMM_DSM);
    cudaFuncSetAttribute(flash_kernel, cudaFuncAttributeMaxDynamicSharedMemorySize, FLASH_SMEM_BYTES);

    // weights -> split bf16 (layout preserved [K,N])
    wsplit<<<HID * HID / 2048, 256>>>(wq, wqh, wql, HID * HID);
    wsplit<<<HID * HID / 2048, 256>>>(wk, wkh, wkl, HID * HID);
    wsplit<<<HID * HID / 2048, 256>>>(wv, wvh, wvl, HID * HID);
    wsplit<<<HID * HID / 2048, 256>>>(wo, woh, wol, HID * HID);
    wsplit<<<HID * FFDIM / 2048, 256>>>(w1, w1h, w1l, HID * FFDIM);
    wsplit<<<FFDIM * HID / 2048, 256>>>(w2, w2h, w2l, FFDIM * HID);

    ln_split<<<ROWS, 128>>>(x1, ln1_g, ln1_b, y1h, y1l);
    ln_split<<<ROWS, 128>>>(x2, ln2_g, ln2_b, y2h, y2l);

    dim3 gP(HID / 128, ROWS / 128);  // (8, 32)
    mma_gemm<<<gP, 256, GEMM_DSM>>>(y2h, y2l, wqh, wql, bq, nullptr, q, nullptr, nullptr,
                                    ROWS, HID, HID, M_F32, 0.125f);
    mma_gemm<<<gP, 256, GEMM_DSM>>>(y1h, y1l, wkh, wkl, bk, nullptr, k, nullptr, nullptr,
                                    ROWS, HID, HID, M_F32, 1.f);
    mma_gemm<<<gP, 256, GEMM_DSM>>>(y1h, y1l, wvh, wvl, bv, nullptr, v, nullptr, nullptr,
                                    ROWS, HID, HID, M_F32, 1.f);

    flash_kernel<<<dim3(64, SEQ / BR), 256, FLASH_SMEM_BYTES>>>(q, k, v, attn_bias, oh, ol);

    mma_gemm<<<gP, 256, GEMM_DSM>>>(oh, ol, woh, wol, bo, x2, x, nullptr, nullptr,
                                    ROWS, HID, HID, M_RES, 1.f);

    ln_split<<<ROWS, 128>>>(x, lnf_g, lnf_b, xlh, xll);

    mma_gemm<<<dim3(FFDIM / 128, ROWS / 128), 256, GEMM_DSM>>>(
        xlh, xll, w1h, w1l, b1, nullptr, nullptr, fh, fl, ROWS, FFDIM, HID, M_GELU, 1.f);
    mma_gemm<<<gP, 256, GEMM_DSM>>>(fh, fl, w2h, w2l, b2, x, out, nullptr, nullptr,
                                    ROWS, HID, FFDIM, M_RES, 1.f);
}

// round 6
// speedup vs baseline: 3.6790x; 1.3320x over previous
#include <cuda_runtime.h>
#include <cuda_bf16.h>
#include <math.h>
#include <stdint.h>

#define BATCH 4
#define SEQ   1024
#define HID   1024
#define DHEAD 64
#define FFDIM 4096
#define ROWS  (BATCH * SEQ)

// scratch
__device__ float g_x[ROWS * HID];
__device__ __nv_bfloat16 g_y1h[ROWS * HID], g_y1l[ROWS * HID];
__device__ __nv_bfloat16 g_y2h[ROWS * HID], g_y2l[ROWS * HID];
__device__ __nv_bfloat16 g_qh [ROWS * HID], g_ql [ROWS * HID];
__device__ __nv_bfloat16 g_kh [ROWS * HID], g_kl [ROWS * HID];
__device__ __nv_bfloat16 g_vh [ROWS * HID], g_vl [ROWS * HID];
__device__ __nv_bfloat16 g_oh [ROWS * HID], g_ol [ROWS * HID];
__device__ __nv_bfloat16 g_xlh[ROWS * HID], g_xll[ROWS * HID];
__device__ __nv_bfloat16 g_fh [ROWS * FFDIM], g_fl[ROWS * FFDIM];
__device__ __nv_bfloat16 g_wqh[HID * HID], g_wql[HID * HID];
__device__ __nv_bfloat16 g_wkh[HID * HID], g_wkl[HID * HID];
__device__ __nv_bfloat16 g_wvh[HID * HID], g_wvl[HID * HID];
__device__ __nv_bfloat16 g_woh[HID * HID], g_wol[HID * HID];
__device__ __nv_bfloat16 g_w1h[HID * FFDIM], g_w1l[HID * FFDIM];
__device__ __nv_bfloat16 g_w2h[FFDIM * HID], g_w2l[FFDIM * HID];

// ---------------- helpers ----------------
__device__ __forceinline__ uint32_t smem_u32(const void* p) {
    uint32_t a;
    asm("{ .reg .u64 t; cvta.to.shared.u64 t, %1; cvt.u32.u64 %0, t; }" : "=r"(a) : "l"(p));
    return a;
}
#define CP_ASYNC16(dst, src) \
    asm volatile("cp.async.cg.shared.global [%0], [%1], 16;" :: "r"(dst), "l"(src) : "memory")
#define CP_COMMIT() asm volatile("cp.async.commit_group;" ::: "memory")
#define CP_WAIT1()  asm volatile("cp.async.wait_group 1;" ::: "memory")
#define CP_WAIT0()  asm volatile("cp.async.wait_group 0;" ::: "memory")

#define LDX4(r, a) \
    asm volatile("ldmatrix.sync.aligned.m8n8.x4.shared.b16 {%0,%1,%2,%3}, [%4];" \
        : "=r"((r)[0]), "=r"((r)[1]), "=r"((r)[2]), "=r"((r)[3]) : "r"(a))
#define LDX4T(r, a) \
    asm volatile("ldmatrix.sync.aligned.m8n8.x4.trans.shared.b16 {%0,%1,%2,%3}, [%4];" \
        : "=r"((r)[0]), "=r"((r)[1]), "=r"((r)[2]), "=r"((r)[3]) : "r"(a))

__device__ __forceinline__ void mma_bf16(float* d, const uint32_t* a, const uint32_t* b) {
    asm volatile(
        "mma.sync.aligned.m16n8k16.row.col.f32.bf16.bf16.f32 "
        "{%0,%1,%2,%3}, {%4,%5,%6,%7}, {%8,%9}, {%0,%1,%2,%3};"
        : "+f"(d[0]), "+f"(d[1]), "+f"(d[2]), "+f"(d[3])
        : "r"(a[0]), "r"(a[1]), "r"(a[2]), "r"(a[3]), "r"(b[0]), "r"(b[1]));
}

__device__ __forceinline__ void splitpack(const float* v, uint4& H, uint4& L) {
    uint32_t h[4], l[4];
    #pragma unroll
    for (int p = 0; p < 4; p++) {
        __nv_bfloat16 h0 = __float2bfloat16(v[2*p]), h1 = __float2bfloat16(v[2*p+1]);
        float r0 = v[2*p] - __bfloat162float(h0), r1 = v[2*p+1] - __bfloat162float(h1);
        __nv_bfloat16 l0 = __float2bfloat16(r0), l1 = __float2bfloat16(r1);
        h[p] = ((uint32_t)__bfloat16_as_ushort(h1) << 16) | __bfloat16_as_ushort(h0);
        l[p] = ((uint32_t)__bfloat16_as_ushort(l1) << 16) | __bfloat16_as_ushort(l0);
    }
    H = make_uint4(h[0], h[1], h[2], h[3]);
    L = make_uint4(l[0], l[1], l[2], l[3]);
}
// pack 2 floats -> (hi bf16x2, lo bf16x2)
__device__ __forceinline__ void pack2(float v0, float v1, uint32_t& H, uint32_t& L) {
    __nv_bfloat16 h0 = __float2bfloat16(v0), h1 = __float2bfloat16(v1);
    float r0 = v0 - __bfloat162float(h0), r1 = v1 - __bfloat162float(h1);
    __nv_bfloat16 l0 = __float2bfloat16(r0), l1 = __float2bfloat16(r1);
    H = ((uint32_t)__bfloat16_as_ushort(h1) << 16) | __bfloat16_as_ushort(h0);
    L = ((uint32_t)__bfloat16_as_ushort(l1) << 16) | __bfloat16_as_ushort(l0);
}
__device__ __forceinline__ float gelu_exact(float v) {
    return 0.5f * v * (1.0f + erff(v * 0.70710678118654752f));
}

// ---------------- weight split ----------------
__global__ __launch_bounds__(256)
void wsplit(const float* __restrict__ w, __nv_bfloat16* __restrict__ h,
            __nv_bfloat16* __restrict__ l, int n)
{
    int i = (blockIdx.x * 256 + threadIdx.x) * 8;
    if (i >= n) return;
    float v[8];
    *(float4*)&v[0] = *(const float4*)(w + i);
    *(float4*)&v[4] = *(const float4*)(w + i + 4);
    uint4 H, L; splitpack(v, H, L);
    *(uint4*)(h + i) = H;
    *(uint4*)(l + i) = L;
}

// ---------------- LayerNorm -> bf16 hi/lo ----------------
__global__ __launch_bounds__(128)
void ln_split(const float* __restrict__ x, const float* __restrict__ g,
              const float* __restrict__ b, __nv_bfloat16* __restrict__ yh,
              __nv_bfloat16* __restrict__ yl)
{
    int row = blockIdx.x, t = threadIdx.x;
    const float4* xr = (const float4*)(x + (size_t)row * HID);
    float4 a0 = xr[t * 2], a1 = xr[t * 2 + 1];
    float s  = a0.x + a0.y + a0.z + a0.w + a1.x + a1.y + a1.z + a1.w;
    float ss = a0.x*a0.x + a0.y*a0.y + a0.z*a0.z + a0.w*a0.w
             + a1.x*a1.x + a1.y*a1.y + a1.z*a1.z + a1.w*a1.w;
    #pragma unroll
    for (int o2 = 16; o2; o2 >>= 1) {
        s  += __shfl_xor_sync(0xffffffffu, s,  o2);
        ss += __shfl_xor_sync(0xffffffffu, ss, o2);
    }
    __shared__ float rs[4], rss[4];
    __shared__ float smean, srstd;
    int w = t >> 5;
    if ((t & 31) == 0) { rs[w] = s; rss[w] = ss; }
    __syncthreads();
    if (t == 0) {
        float S = rs[0]+rs[1]+rs[2]+rs[3], SS = rss[0]+rss[1]+rss[2]+rss[3];
        float mean = S * (1.f / HID);
        smean = mean;
        srstd = rsqrtf(SS * (1.f / HID) - mean * mean + 1e-5f);
    }
    __syncthreads();
    float mean = smean, rstd = srstd;
    const float4* gp = (const float4*)g; const float4* bp = (const float4*)b;
    float4 g0 = gp[t*2], g1 = gp[t*2+1], b0 = bp[t*2], b1 = bp[t*2+1];
    float v[8];
    v[0]=(a0.x-mean)*rstd*g0.x+b0.x; v[1]=(a0.y-mean)*rstd*g0.y+b0.y;
    v[2]=(a0.z-mean)*rstd*g0.z+b0.z; v[3]=(a0.w-mean)*rstd*g0.w+b0.w;
    v[4]=(a1.x-mean)*rstd*g1.x+b1.x; v[5]=(a1.y-mean)*rstd*g1.y+b1.y;
    v[6]=(a1.z-mean)*rstd*g1.z+b1.z; v[7]=(a1.w-mean)*rstd*g1.w+b1.w;
    uint4 H, L; splitpack(v, H, L);
    ((uint4*)yh)[(size_t)row * 128 + t] = H;
    ((uint4*)yl)[(size_t)row * 128 + t] = L;
}

// ---------------- mma.sync GEMM (validated in R5) ----------------
#define STAGE_B 65536
#define GEMM_DSM (2 * STAGE_B)
enum { M_F32 = 0, M_RES = 1, M_GELU = 2, M_SPLIT = 3 };

__global__ __launch_bounds__(256)
void mma_gemm(const __nv_bfloat16* __restrict__ Ah, const __nv_bfloat16* __restrict__ Al,
              const __nv_bfloat16* __restrict__ Bh, const __nv_bfloat16* __restrict__ Bl,
              const float* __restrict__ bias, const float* __restrict__ res,
              float* __restrict__ outF, __nv_bfloat16* __restrict__ outH,
              __nv_bfloat16* __restrict__ outL, int M, int N, int K,
              int mode, float scale)
{
    extern __shared__ __align__(1024) char dsm[];
    const uint32_t base = smem_u32(dsm);
    int tid = threadIdx.x;
    int m0 = blockIdx.y * 128, n0 = blockIdx.x * 128;
    int nch = K >> 6;

    auto issue = [&](int c, int st) {
        uint32_t sb = base + st * STAGE_B;
        #pragma unroll
        for (int i = 0; i < 4; i++) {
            int idx = tid + i * 256;
            int r = idx >> 3, g = idx & 7;
            const __nv_bfloat16* sh = Ah + (size_t)(m0 + r) * K + c * 64 + g * 8;
            const __nv_bfloat16* sl = Al + (size_t)(m0 + r) * K + c * 64 + g * 8;
            uint32_t d = sb + r * 128 + ((g ^ (r & 7)) << 4);
            CP_ASYNC16(d, sh);
            CP_ASYNC16(d + 16384, sl);
        }
        #pragma unroll
        for (int i = 0; i < 4; i++) {
            int idx = tid + i * 256;
            int r = idx >> 4, g = idx & 15;
            const __nv_bfloat16* sh = Bh + (size_t)(c * 64 + r) * N + n0 + g * 8;
            const __nv_bfloat16* sl = Bl + (size_t)(c * 64 + r) * N + n0 + g * 8;
            uint32_t pg = (g & 8) | ((g ^ (r & 7)) & 7);
            uint32_t d = sb + 32768 + r * 256 + (pg << 4);
            CP_ASYNC16(d, sh);
            CP_ASYNC16(d + 16384, sl);
        }
        CP_COMMIT();
    };

    int w = tid >> 5, t = tid & 31;
    int mrow_loc = (w & 3) * 32;
    int ncol_loc = (w >> 2) * 64;
    int gt = t >> 4;
    int rl = t & 15;
    int xa = rl & 7;

    float acc[2][8][4] = {};

    issue(0, 0);
    if (nch > 1) issue(1, 1);

    for (int c = 0; c < nch; c++) {
        if (c + 1 < nch) { CP_WAIT1(); } else { CP_WAIT0(); }
        __syncthreads();
        uint32_t sb = base + (c & 1) * STAGE_B;
        uint32_t aB = sb + (mrow_loc + rl) * 128;
        uint32_t bB = sb + 32768 + rl * 256;
        #pragma unroll
        for (int s = 0; s < 4; s++) {
            uint32_t Ahf[2][4], Alf[2][4];
            #pragma unroll
            for (int mt = 0; mt < 2; mt++) {
                uint32_t ad = aB + mt * 2048 + (((s * 2 + gt) ^ xa) << 4);
                LDX4(Ahf[mt], ad);
                LDX4(Alf[mt], ad + 16384);
            }
            #pragma unroll
            for (int ni = 0; ni < 4; ni++) {
                int g = (ncol_loc >> 4) * 2 + ni * 2 + gt;
                uint32_t pg = (g & 8) | ((g ^ xa) & 7);
                uint32_t bd = bB + s * 4096 + (pg << 4);
                uint32_t Bhf[4], Blf[4];
                LDX4T(Bhf, bd);
                LDX4T(Blf, bd + 16384);
                #pragma unroll
                for (int mt = 0; mt < 2; mt++) {
                    #pragma unroll
                    for (int nj = 0; nj < 2; nj++) {
                        float* d = acc[mt][ni * 2 + nj];
                        mma_bf16(d, Ahf[mt], Bhf + nj * 2);
                        mma_bf16(d, Ahf[mt], Blf + nj * 2);
                        mma_bf16(d, Alf[mt], Bhf + nj * 2);
                    }
                }
            }
        }
        __syncthreads();
        if (c + 2 < nch) issue(c + 2, c & 1);
    }

    int qr = t >> 2, qc = t & 3;
    #pragma unroll
    for (int mt = 0; mt < 2; mt++) {
        #pragma unroll
        for (int nf = 0; nf < 8; nf++) {
            int col = n0 + ncol_loc + nf * 8 + qc * 2;
            float2 bv = *(const float2*)(bias + col);
            #pragma unroll
            for (int half = 0; half < 2; half++) {
                int row = m0 + mrow_loc + mt * 16 + qr + half * 8;
                float v0 = acc[mt][nf][half * 2 + 0] + bv.x;
                float v1 = acc[mt][nf][half * 2 + 1] + bv.y;
                size_t off = (size_t)row * N + col;
                if (mode >= M_GELU) {
                    if (mode == M_GELU) { v0 = gelu_exact(v0); v1 = gelu_exact(v1); }
                    else { v0 *= scale; v1 *= scale; }
                    uint32_t H, L;
                    pack2(v0, v1, H, L);
                    *(uint32_t*)(outH + off) = H;
                    *(uint32_t*)(outL + off) = L;
                } else {
                    v0 *= scale; v1 *= scale;
                    if (mode == M_RES) {
                        float2 rv = *(const float2*)(res + off);
                        v0 += rv.x; v1 += rv.y;
                    }
                    *(float2*)(outF + off) = make_float2(v0, v1);
                }
            }
        }
    }
}

// ---------------- Flash attention on mma.sync (split bf16) ----------------
// CTA: 64 q-rows, 4 warps (m16 each); Bc=64, D=64.
// smem: Qh 0, Ql 8K, Kh 16K, Kl 24K, Vh 32K, Vl 40K  (48KB static)
__global__ __launch_bounds__(128)
void flash_mma(const __nv_bfloat16* __restrict__ Qh, const __nv_bfloat16* __restrict__ Ql,
               const __nv_bfloat16* __restrict__ Kgh, const __nv_bfloat16* __restrict__ Kgl,
               const __nv_bfloat16* __restrict__ Vgh, const __nv_bfloat16* __restrict__ Vgl,
               const float* __restrict__ bias,
               __nv_bfloat16* __restrict__ Oh, __nv_bfloat16* __restrict__ Ol)
{
    __shared__ __align__(1024) char sm[49152];
    const uint32_t sb = smem_u32(sm);
    int bh = blockIdx.x, b = bh >> 4, h = bh & 15;
    int q0 = blockIdx.y * 64;
    int tid = threadIdx.x, w = tid >> 5, lane = tid & 31;

    // load Q tiles (hi/lo)
    {
        const __nv_bfloat16* qgh = Qh + ((size_t)(b * SEQ + q0)) * HID + h * 64;
        const __nv_bfloat16* qgl = Ql + ((size_t)(b * SEQ + q0)) * HID + h * 64;
        #pragma unroll
        for (int i = 0; i < 4; i++) {
            int idx = tid + i * 128;
            int r = idx >> 3, g = idx & 7;
            uint32_t d = sb + r * 128 + ((g ^ (r & 7)) << 4);
            CP_ASYNC16(d, qgh + (size_t)r * HID + g * 8);
            CP_ASYNC16(d + 8192, qgl + (size_t)r * HID + g * 8);
        }
    }
    auto issueKV = [&](int k0) {
        const __nv_bfloat16* kgh = Kgh + ((size_t)(b * SEQ + k0)) * HID + h * 64;
        const __nv_bfloat16* kgl = Kgl + ((size_t)(b * SEQ + k0)) * HID + h * 64;
        const __nv_bfloat16* vgh = Vgh + ((size_t)(b * SEQ + k0)) * HID + h * 64;
        const __nv_bfloat16* vgl = Vgl + ((size_t)(b * SEQ + k0)) * HID + h * 64;
        #pragma unroll
        for (int i = 0; i < 4; i++) {
            int idx = tid + i * 128;
            int r = idx >> 3, g = idx & 7;
            uint32_t d = sb + r * 128 + ((g ^ (r & 7)) << 4);
            size_t go = (size_t)r * HID + g * 8;
            CP_ASYNC16(d + 16384, kgh + go);
            CP_ASYNC16(d + 24576, kgl + go);
            CP_ASYNC16(d + 32768, vgh + go);
            CP_ASYNC16(d + 40960, vgl + go);
        }
        CP_COMMIT();
    };

    issueKV(0);

    int wq0 = w * 16;
    int rl = lane & 15, gt = lane >> 4, xa = rl & 7;
    int qr = lane >> 2, qc = lane & 3;

    float oacc[8][4] = {};
    float mrow0 = -1e30f, mrow1 = -1e30f, lrow0 = 0.f, lrow1 = 0.f;

    for (int kt = 0; kt < 16; kt++) {
        CP_WAIT0();
        __syncthreads();

        // ---- S = Q @ K^T (split bf16) ----
        float sacc[8][4] = {};
        #pragma unroll
        for (int s = 0; s < 4; s++) {
            uint32_t qa = sb + (wq0 + rl) * 128 + (((s * 2 + gt) ^ xa) << 4);
            uint32_t Qhf[4], Qlf[4];
            LDX4(Qhf, qa);
            LDX4(Qlf, qa + 8192);
            #pragma unroll
            for (int ni = 0; ni < 4; ni++) {
                uint32_t ka = sb + 16384 + (ni * 16 + rl) * 128 + (((s * 2 + gt) ^ xa) << 4);
                uint32_t Kh4[4], Kl4[4];
                LDX4(Kh4, ka);
                LDX4(Kl4, ka + 8192);
                uint32_t f0h[2] = {Kh4[0], Kh4[2]}, f1h[2] = {Kh4[1], Kh4[3]};
                uint32_t f0l[2] = {Kl4[0], Kl4[2]}, f1l[2] = {Kl4[1], Kl4[3]};
                mma_bf16(sacc[ni * 2],     Qhf, f0h);
                mma_bf16(sacc[ni * 2],     Qhf, f0l);
                mma_bf16(sacc[ni * 2],     Qlf, f0h);
                mma_bf16(sacc[ni * 2 + 1], Qhf, f1h);
                mma_bf16(sacc[ni * 2 + 1], Qhf, f1l);
                mma_bf16(sacc[ni * 2 + 1], Qlf, f1h);
            }
        }

        // ---- bias + online softmax (registers) ----
        {
            const float* bb = bias + ((size_t)bh * SEQ + q0 + wq0 + qr) * SEQ
                            + kt * 64 + qc * 2;
            #pragma unroll
            for (int f = 0; f < 8; f++) {
                float2 b0 = *(const float2*)(bb + f * 8);
                float2 b1 = *(const float2*)(bb + 8 * SEQ + f * 8);
                sacc[f][0] += b0.x; sacc[f][1] += b0.y;
                sacc[f][2] += b1.x; sacc[f][3] += b1.y;
            }
            float mx0 = -1e30f, mx1 = -1e30f;
            #pragma unroll
            for (int f = 0; f < 8; f++) {
                mx0 = fmaxf(mx0, fmaxf(sacc[f][0], sacc[f][1]));
                mx1 = fmaxf(mx1, fmaxf(sacc[f][2], sacc[f][3]));
            }
            mx0 = fmaxf(mx0, __shfl_xor_sync(0xffffffffu, mx0, 1));
            mx0 = fmaxf(mx0, __shfl_xor_sync(0xffffffffu, mx0, 2));
            mx1 = fmaxf(mx1, __shfl_xor_sync(0xffffffffu, mx1, 1));
            mx1 = fmaxf(mx1, __shfl_xor_sync(0xffffffffu, mx1, 2));
            float mn0 = fmaxf(mrow0, mx0), mn1 = fmaxf(mrow1, mx1);
            float sf0 = __expf(mrow0 - mn0), sf1 = __expf(mrow1 - mn1);
            float sum0 = 0.f, sum1 = 0.f;
            #pragma unroll
            for (int f = 0; f < 8; f++) {
                float p0 = __expf(sacc[f][0] - mn0);
                float p1 = __expf(sacc[f][1] - mn0);
                float p2 = __expf(sacc[f][2] - mn1);
                float p3 = __expf(sacc[f][3] - mn1);
                sacc[f][0] = p0; sacc[f][1] = p1; sacc[f][2] = p2; sacc[f][3] = p3;
                sum0 += p0 + p1; sum1 += p2 + p3;
            }
            sum0 += __shfl_xor_sync(0xffffffffu, sum0, 1);
            sum0 += __shfl_xor_sync(0xffffffffu, sum0, 2);
            sum1 += __shfl_xor_sync(0xffffffffu, sum1, 1);
            sum1 += __shfl_xor_sync(0xffffffffu, sum1, 2);
            mrow0 = mn0; mrow1 = mn1;
            lrow0 = lrow0 * sf0 + sum0;
            lrow1 = lrow1 * sf1 + sum1;
            #pragma unroll
            for (int f = 0; f < 8; f++) {
                oacc[f][0] *= sf0; oacc[f][1] *= sf0;
                oacc[f][2] *= sf1; oacc[f][3] *= sf1;
            }
        }

        // ---- O += P @ V (split bf16) ----
        #pragma unroll
        for (int kb = 0; kb < 4; kb++) {
            uint32_t pah[4], pal[4];
            pack2(sacc[2*kb][0],   sacc[2*kb][1],   pah[0], pal[0]);
            pack2(sacc[2*kb][2],   sacc[2*kb][3],   pah[1], pal[1]);
            pack2(sacc[2*kb+1][0], sacc[2*kb+1][1], pah[2], pal[2]);
            pack2(sacc[2*kb+1][2], sacc[2*kb+1][3], pah[3], pal[3]);
            #pragma unroll
            for (int di = 0; di < 4; di++) {
                uint32_t va = sb + 32768 + (kb * 16 + rl) * 128
                            + (((di * 2 + gt) ^ xa) << 4);
                uint32_t Vh4[4], Vl4[4];
                LDX4T(Vh4, va);
                LDX4T(Vl4, va + 8192);
                #pragma unroll
                for (int nj = 0; nj < 2; nj++) {
                    float* d = oacc[di * 2 + nj];
                    mma_bf16(d, pah, Vh4 + nj * 2);
                    mma_bf16(d, pah, Vl4 + nj * 2);
                    mma_bf16(d, pal, Vh4 + nj * 2);
                }
            }
        }
        __syncthreads();
        if (kt + 1 < 16) issueKV((kt + 1) * 64);
    }

    // ---- epilogue: normalize, split, store ----
    float inv0 = 1.f / lrow0, inv1 = 1.f / lrow1;
    size_t row0 = (size_t)(b * SEQ + q0 + wq0 + qr);
    #pragma unroll
    for (int f = 0; f < 8; f++) {
        int col = h * 64 + f * 8 + qc * 2;
        uint32_t H, L;
        pack2(oacc[f][0] * inv0, oacc[f][1] * inv0, H, L);
        *(uint32_t*)(Oh + row0 * HID + col) = H;
        *(uint32_t*)(Ol + row0 * HID + col) = L;
        pack2(oacc[f][2] * inv1, oacc[f][3] * inv1, H, L);
        *(uint32_t*)(Oh + (row0 + 8) * HID + col) = H;
        *(uint32_t*)(Ol + (row0 + 8) * HID + col) = L;
    }
}

// ---------------- launch ----------------
extern "C" void kernel_launch(void* const* d_in, const int* in_sizes, int n_in,
                              void* d_out, int out_size)
{
    const float* x1 = (const float*)d_in[0];
    const float* x2 = (const float*)d_in[1];
    const float* attn_bias = (const float*)d_in[2];
    const float* ln1_g = (const float*)d_in[3];
    const float* ln1_b = (const float*)d_in[4];
    const float* ln2_g = (const float*)d_in[5];
    const float* ln2_b = (const float*)d_in[6];
    const float* wq = (const float*)d_in[7];
    const float* bq = (const float*)d_in[8];
    const float* wk = (const float*)d_in[9];
    const float* bk = (const float*)d_in[10];
    const float* wv = (const float*)d_in[11];
    const float* bv = (const float*)d_in[12];
    const float* wo = (const float*)d_in[13];
    const float* bo = (const float*)d_in[14];
    const float* lnf_g = (const float*)d_in[15];
    const float* lnf_b = (const float*)d_in[16];
    const float* w1 = (const float*)d_in[17];
    const float* b1 = (const float*)d_in[18];
    const float* w2 = (const float*)d_in[19];
    const float* b2 = (const float*)d_in[20];
    float* out = (float*)d_out;

    float* x;
    __nv_bfloat16 *y1h,*y1l,*y2h,*y2l,*qh,*ql,*kh,*kl,*vh,*vl,*oh,*ol,*xlh,*xll,*fh,*fl;
    __nv_bfloat16 *wqh,*wql,*wkh,*wkl,*wvh,*wvl,*woh,*wol,*w1h,*w1l,*w2h,*w2l;
    cudaGetSymbolAddress((void**)&x, g_x);
    cudaGetSymbolAddress((void**)&y1h, g_y1h); cudaGetSymbolAddress((void**)&y1l, g_y1l);
    cudaGetSymbolAddress((void**)&y2h, g_y2h); cudaGetSymbolAddress((void**)&y2l, g_y2l);
    cudaGetSymbolAddress((void**)&qh, g_qh);   cudaGetSymbolAddress((void**)&ql, g_ql);
    cudaGetSymbolAddress((void**)&kh, g_kh);   cudaGetSymbolAddress((void**)&kl, g_kl);
    cudaGetSymbolAddress((void**)&vh, g_vh);   cudaGetSymbolAddress((void**)&vl, g_vl);
    cudaGetSymbolAddress((void**)&oh, g_oh);   cudaGetSymbolAddress((void**)&ol, g_ol);
    cudaGetSymbolAddress((void**)&xlh, g_xlh); cudaGetSymbolAddress((void**)&xll, g_xll);
    cudaGetSymbolAddress((void**)&fh, g_fh);   cudaGetSymbolAddress((void**)&fl, g_fl);
    cudaGetSymbolAddress((void**)&wqh, g_wqh); cudaGetSymbolAddress((void**)&wql, g_wql);
    cudaGetSymbolAddress((void**)&wkh, g_wkh); cudaGetSymbolAddress((void**)&wkl, g_wkl);
    cudaGetSymbolAddress((void**)&wvh, g_wvh); cudaGetSymbolAddress((void**)&wvl, g_wvl);
    cudaGetSymbolAddress((void**)&woh, g_woh); cudaGetSymbolAddress((void**)&wol, g_wol);
    cudaGetSymbolAddress((void**)&w1h, g_w1h); cudaGetSymbolAddress((void**)&w1l, g_w1l);
    cudaGetSymbolAddress((void**)&w2h, g_w2h); cudaGetSymbolAddress((void**)&w2l, g_w2l);

    cudaFuncSetAttribute(mma_gemm, cudaFuncAttributeMaxDynamicSharedMemorySize, GEMM_DSM);

    wsplit<<<HID * HID / 2048, 256>>>(wq, wqh, wql, HID * HID);
    wsplit<<<HID * HID / 2048, 256>>>(wk, wkh, wkl, HID * HID);
    wsplit<<<HID * HID / 2048, 256>>>(wv, wvh, wvl, HID * HID);
    wsplit<<<HID * HID / 2048, 256>>>(wo, woh, wol, HID * HID);
    wsplit<<<HID * FFDIM / 2048, 256>>>(w1, w1h, w1l, HID * FFDIM);
    wsplit<<<FFDIM * HID / 2048, 256>>>(w2, w2h, w2l, FFDIM * HID);

    ln_split<<<ROWS, 128>>>(x1, ln1_g, ln1_b, y1h, y1l);
    ln_split<<<ROWS, 128>>>(x2, ln2_g, ln2_b, y2h, y2l);

    dim3 gP(HID / 128, ROWS / 128);  // (8, 32)
    mma_gemm<<<gP, 256, GEMM_DSM>>>(y2h, y2l, wqh, wql, bq, nullptr, nullptr, qh, ql,
                                    ROWS, HID, HID, M_SPLIT, 0.125f);
    mma_gemm<<<gP, 256, GEMM_DSM>>>(y1h, y1l, wkh, wkl, bk, nullptr, nullptr, kh, kl,
                                    ROWS, HID, HID, M_SPLIT, 1.f);
    mma_gemm<<<gP, 256, GEMM_DSM>>>(y1h, y1l, wvh, wvl, bv, nullptr, nullptr, vh, vl,
                                    ROWS, HID, HID, M_SPLIT, 1.f);

    flash_mma<<<dim3(64, 16), 128>>>(qh, ql, kh, kl, vh, vl, attn_bias, oh, ol);

    mma_gemm<<<gP, 256, GEMM_DSM>>>(oh, ol, woh, wol, bo, x2, x, nullptr, nullptr,
                                    ROWS, HID, HID, M_RES, 1.f);

    ln_split<<<ROWS, 128>>>(x, lnf_g, lnf_b, xlh, xll);

    mma_gemm<<<dim3(FFDIM / 128, ROWS / 128), 256, GEMM_DSM>>>(
        xlh, xll, w1h, w1l, b1, nullptr, nullptr, fh, fl, ROWS, FFDIM, HID, M_GELU, 1.f);
    mma_gemm<<<gP, 256, GEMM_DSM>>>(fh, fl, w2h, w2l, b2, x, out, nullptr, nullptr,
                                    ROWS, HID, FFDIM, M_RES, 1.f);
}

// round 7
// speedup vs baseline: 3.6877x; 1.0024x over previous
#include <cuda_runtime.h>
#include <cuda_bf16.h>
#include <math.h>
#include <stdint.h>

#define BATCH 4
#define SEQ   1024
#define HID   1024
#define DHEAD 64
#define FFDIM 4096
#define ROWS  (BATCH * SEQ)

// scratch
__device__ float g_x[ROWS * HID];
__device__ __nv_bfloat16 g_y1h[ROWS * HID], g_y1l[ROWS * HID];
__device__ __nv_bfloat16 g_y2h[ROWS * HID], g_y2l[ROWS * HID];
__device__ __nv_bfloat16 g_qh [ROWS * HID], g_ql [ROWS * HID];
__device__ __nv_bfloat16 g_kh [ROWS * HID], g_kl [ROWS * HID];
__device__ __nv_bfloat16 g_vh [ROWS * HID], g_vl [ROWS * HID];
__device__ __nv_bfloat16 g_oh [ROWS * HID], g_ol [ROWS * HID];
__device__ __nv_bfloat16 g_xlh[ROWS * HID], g_xll[ROWS * HID];
__device__ __nv_bfloat16 g_fh [ROWS * FFDIM], g_fl[ROWS * FFDIM];
__device__ __nv_bfloat16 g_wqh[HID * HID], g_wql[HID * HID];
__device__ __nv_bfloat16 g_wkh[HID * HID], g_wkl[HID * HID];
__device__ __nv_bfloat16 g_wvh[HID * HID], g_wvl[HID * HID];
__device__ __nv_bfloat16 g_woh[HID * HID], g_wol[HID * HID];
__device__ __nv_bfloat16 g_w1h[HID * FFDIM], g_w1l[HID * FFDIM];
__device__ __nv_bfloat16 g_w2h[FFDIM * HID], g_w2l[FFDIM * HID];

// ---------------- helpers ----------------
__device__ __forceinline__ uint32_t smem_u32(const void* p) {
    uint32_t a;
    asm("{ .reg .u64 t; cvta.to.shared.u64 t, %1; cvt.u32.u64 %0, t; }" : "=r"(a) : "l"(p));
    return a;
}
#define CP_ASYNC16(dst, src) \
    asm volatile("cp.async.cg.shared.global [%0], [%1], 16;" :: "r"(dst), "l"(src) : "memory")
#define CP_COMMIT() asm volatile("cp.async.commit_group;" ::: "memory")
#define CP_WAIT1()  asm volatile("cp.async.wait_group 1;" ::: "memory")
#define CP_WAIT0()  asm volatile("cp.async.wait_group 0;" ::: "memory")

#define LDX4(r, a) \
    asm volatile("ldmatrix.sync.aligned.m8n8.x4.shared.b16 {%0,%1,%2,%3}, [%4];" \
        : "=r"((r)[0]), "=r"((r)[1]), "=r"((r)[2]), "=r"((r)[3]) : "r"(a))
#define LDX4T(r, a) \
    asm volatile("ldmatrix.sync.aligned.m8n8.x4.trans.shared.b16 {%0,%1,%2,%3}, [%4];" \
        : "=r"((r)[0]), "=r"((r)[1]), "=r"((r)[2]), "=r"((r)[3]) : "r"(a))

__device__ __forceinline__ void mma_bf16(float* d, const uint32_t* a, const uint32_t* b) {
    asm volatile(
        "mma.sync.aligned.m16n8k16.row.col.f32.bf16.bf16.f32 "
        "{%0,%1,%2,%3}, {%4,%5,%6,%7}, {%8,%9}, {%0,%1,%2,%3};"
        : "+f"(d[0]), "+f"(d[1]), "+f"(d[2]), "+f"(d[3])
        : "r"(a[0]), "r"(a[1]), "r"(a[2]), "r"(a[3]), "r"(b[0]), "r"(b[1]));
}

__device__ __forceinline__ void splitpack(const float* v, uint4& H, uint4& L) {
    uint32_t h[4], l[4];
    #pragma unroll
    for (int p = 0; p < 4; p++) {
        __nv_bfloat16 h0 = __float2bfloat16(v[2*p]), h1 = __float2bfloat16(v[2*p+1]);
        float r0 = v[2*p] - __bfloat162float(h0), r1 = v[2*p+1] - __bfloat162float(h1);
        __nv_bfloat16 l0 = __float2bfloat16(r0), l1 = __float2bfloat16(r1);
        h[p] = ((uint32_t)__bfloat16_as_ushort(h1) << 16) | __bfloat16_as_ushort(h0);
        l[p] = ((uint32_t)__bfloat16_as_ushort(l1) << 16) | __bfloat16_as_ushort(l0);
    }
    H = make_uint4(h[0], h[1], h[2], h[3]);
    L = make_uint4(l[0], l[1], l[2], l[3]);
}
// pack 2 floats -> (hi bf16x2, lo bf16x2)
__device__ __forceinline__ void pack2(float v0, float v1, uint32_t& H, uint32_t& L) {
    __nv_bfloat16 h0 = __float2bfloat16(v0), h1 = __float2bfloat16(v1);
    float r0 = v0 - __bfloat162float(h0), r1 = v1 - __bfloat162float(h1);
    __nv_bfloat16 l0 = __float2bfloat16(r0), l1 = __float2bfloat16(r1);
    H = ((uint32_t)__bfloat16_as_ushort(h1) << 16) | __bfloat16_as_ushort(h0);
    L = ((uint32_t)__bfloat16_as_ushort(l1) << 16) | __bfloat16_as_ushort(l0);
}
__device__ __forceinline__ float gelu_exact(float v) {
    return 0.5f * v * (1.0f + erff(v * 0.70710678118654752f));
}

// ---------------- weight split ----------------
__global__ __launch_bounds__(256)
void wsplit(const float* __restrict__ w, __nv_bfloat16* __restrict__ h,
            __nv_bfloat16* __restrict__ l, int n)
{
    int i = (blockIdx.x * 256 + threadIdx.x) * 8;
    if (i >= n) return;
    float v[8];
    *(float4*)&v[0] = *(const float4*)(w + i);
    *(float4*)&v[4] = *(const float4*)(w + i + 4);
    uint4 H, L; splitpack(v, H, L);
    *(uint4*)(h + i) = H;
    *(uint4*)(l + i) = L;
}

// ---------------- LayerNorm -> bf16 hi/lo ----------------
__global__ __launch_bounds__(128)
void ln_split(const float* __restrict__ x, const float* __restrict__ g,
              const float* __restrict__ b, __nv_bfloat16* __restrict__ yh,
              __nv_bfloat16* __restrict__ yl)
{
    int row = blockIdx.x, t = threadIdx.x;
    const float4* xr = (const float4*)(x + (size_t)row * HID);
    float4 a0 = xr[t * 2], a1 = xr[t * 2 + 1];
    float s  = a0.x + a0.y + a0.z + a0.w + a1.x + a1.y + a1.z + a1.w;
    float ss = a0.x*a0.x + a0.y*a0.y + a0.z*a0.z + a0.w*a0.w
             + a1.x*a1.x + a1.y*a1.y + a1.z*a1.z + a1.w*a1.w;
    #pragma unroll
    for (int o2 = 16; o2; o2 >>= 1) {
        s  += __shfl_xor_sync(0xffffffffu, s,  o2);
        ss += __shfl_xor_sync(0xffffffffu, ss, o2);
    }
    __shared__ float rs[4], rss[4];
    __shared__ float smean, srstd;
    int w = t >> 5;
    if ((t & 31) == 0) { rs[w] = s; rss[w] = ss; }
    __syncthreads();
    if (t == 0) {
        float S = rs[0]+rs[1]+rs[2]+rs[3], SS = rss[0]+rss[1]+rss[2]+rss[3];
        float mean = S * (1.f / HID);
        smean = mean;
        srstd = rsqrtf(SS * (1.f / HID) - mean * mean + 1e-5f);
    }
    __syncthreads();
    float mean = smean, rstd = srstd;
    const float4* gp = (const float4*)g; const float4* bp = (const float4*)b;
    float4 g0 = gp[t*2], g1 = gp[t*2+1], b0 = bp[t*2], b1 = bp[t*2+1];
    float v[8];
    v[0]=(a0.x-mean)*rstd*g0.x+b0.x; v[1]=(a0.y-mean)*rstd*g0.y+b0.y;
    v[2]=(a0.z-mean)*rstd*g0.z+b0.z; v[3]=(a0.w-mean)*rstd*g0.w+b0.w;
    v[4]=(a1.x-mean)*rstd*g1.x+b1.x; v[5]=(a1.y-mean)*rstd*g1.y+b1.y;
    v[6]=(a1.z-mean)*rstd*g1.z+b1.z; v[7]=(a1.w-mean)*rstd*g1.w+b1.w;
    uint4 H, L; splitpack(v, H, L);
    ((uint4*)yh)[(size_t)row * 128 + t] = H;
    ((uint4*)yl)[(size_t)row * 128 + t] = L;
}

// ---------------- mma.sync GEMM (validated in R5) ----------------
#define STAGE_B 65536
#define GEMM_DSM (2 * STAGE_B)
enum { M_F32 = 0, M_RES = 1, M_GELU = 2, M_SPLIT = 3 };

__global__ __launch_bounds__(256)
void mma_gemm(const __nv_bfloat16* __restrict__ Ah, const __nv_bfloat16* __restrict__ Al,
              const __nv_bfloat16* __restrict__ Bh, const __nv_bfloat16* __restrict__ Bl,
              const float* __restrict__ bias, const float* __restrict__ res,
              float* __restrict__ outF, __nv_bfloat16* __restrict__ outH,
              __nv_bfloat16* __restrict__ outL, int M, int N, int K,
              int mode, float scale)
{
    extern __shared__ __align__(1024) char dsm[];
    const uint32_t base = smem_u32(dsm);
    int tid = threadIdx.x;
    int m0 = blockIdx.y * 128, n0 = blockIdx.x * 128;
    int nch = K >> 6;

    auto issue = [&](int c, int st) {
        uint32_t sb = base + st * STAGE_B;
        #pragma unroll
        for (int i = 0; i < 4; i++) {
            int idx = tid + i * 256;
            int r = idx >> 3, g = idx & 7;
            const __nv_bfloat16* sh = Ah + (size_t)(m0 + r) * K + c * 64 + g * 8;
            const __nv_bfloat16* sl = Al + (size_t)(m0 + r) * K + c * 64 + g * 8;
            uint32_t d = sb + r * 128 + ((g ^ (r & 7)) << 4);
            CP_ASYNC16(d, sh);
            CP_ASYNC16(d + 16384, sl);
        }
        #pragma unroll
        for (int i = 0; i < 4; i++) {
            int idx = tid + i * 256;
            int r = idx >> 4, g = idx & 15;
            const __nv_bfloat16* sh = Bh + (size_t)(c * 64 + r) * N + n0 + g * 8;
            const __nv_bfloat16* sl = Bl + (size_t)(c * 64 + r) * N + n0 + g * 8;
            uint32_t pg = (g & 8) | ((g ^ (r & 7)) & 7);
            uint32_t d = sb + 32768 + r * 256 + (pg << 4);
            CP_ASYNC16(d, sh);
            CP_ASYNC16(d + 16384, sl);
        }
        CP_COMMIT();
    };

    int w = tid >> 5, t = tid & 31;
    int mrow_loc = (w & 3) * 32;
    int ncol_loc = (w >> 2) * 64;
    int gt = t >> 4;
    int rl = t & 15;
    int xa = rl & 7;

    float acc[2][8][4] = {};

    issue(0, 0);
    if (nch > 1) issue(1, 1);

    for (int c = 0; c < nch; c++) {
        if (c + 1 < nch) { CP_WAIT1(); } else { CP_WAIT0(); }
        __syncthreads();
        uint32_t sb = base + (c & 1) * STAGE_B;
        uint32_t aB = sb + (mrow_loc + rl) * 128;
        uint32_t bB = sb + 32768 + rl * 256;
        #pragma unroll
        for (int s = 0; s < 4; s++) {
            uint32_t Ahf[2][4], Alf[2][4];
            #pragma unroll
            for (int mt = 0; mt < 2; mt++) {
                uint32_t ad = aB + mt * 2048 + (((s * 2 + gt) ^ xa) << 4);
                LDX4(Ahf[mt], ad);
                LDX4(Alf[mt], ad + 16384);
            }
            #pragma unroll
            for (int ni = 0; ni < 4; ni++) {
                int g = (ncol_loc >> 4) * 2 + ni * 2 + gt;
                uint32_t pg = (g & 8) | ((g ^ xa) & 7);
                uint32_t bd = bB + s * 4096 + (pg << 4);
                uint32_t Bhf[4], Blf[4];
                LDX4T(Bhf, bd);
                LDX4T(Blf, bd + 16384);
                #pragma unroll
                for (int mt = 0; mt < 2; mt++) {
                    #pragma unroll
                    for (int nj = 0; nj < 2; nj++) {
                        float* d = acc[mt][ni * 2 + nj];
                        mma_bf16(d, Ahf[mt], Bhf + nj * 2);
                        mma_bf16(d, Ahf[mt], Blf + nj * 2);
                        mma_bf16(d, Alf[mt], Bhf + nj * 2);
                    }
                }
            }
        }
        __syncthreads();
        if (c + 2 < nch) issue(c + 2, c & 1);
    }

    int qr = t >> 2, qc = t & 3;
    #pragma unroll
    for (int mt = 0; mt < 2; mt++) {
        #pragma unroll
        for (int nf = 0; nf < 8; nf++) {
            int col = n0 + ncol_loc + nf * 8 + qc * 2;
            float2 bv = *(const float2*)(bias + col);
            #pragma unroll
            for (int half = 0; half < 2; half++) {
                int row = m0 + mrow_loc + mt * 16 + qr + half * 8;
                float v0 = acc[mt][nf][half * 2 + 0] + bv.x;
                float v1 = acc[mt][nf][half * 2 + 1] + bv.y;
                size_t off = (size_t)row * N + col;
                if (mode >= M_GELU) {
                    if (mode == M_GELU) { v0 = gelu_exact(v0); v1 = gelu_exact(v1); }
                    else { v0 *= scale; v1 *= scale; }
                    uint32_t H, L;
                    pack2(v0, v1, H, L);
                    *(uint32_t*)(outH + off) = H;
                    *(uint32_t*)(outL + off) = L;
                } else {
                    v0 *= scale; v1 *= scale;
                    if (mode == M_RES) {
                        float2 rv = *(const float2*)(res + off);
                        v0 += rv.x; v1 += rv.y;
                    }
                    *(float2*)(outF + off) = make_float2(v0, v1);
                }
            }
        }
    }
}

// ---------------- Flash attention on mma.sync (split bf16) ----------------
// CTA: 64 q-rows, 4 warps (m16 each); Bc=64, D=64.
// smem: Qh 0, Ql 8K, Kh 16K, Kl 24K, Vh 32K, Vl 40K  (48KB static)
__global__ __launch_bounds__(128)
void flash_mma(const __nv_bfloat16* __restrict__ Qh, const __nv_bfloat16* __restrict__ Ql,
               const __nv_bfloat16* __restrict__ Kgh, const __nv_bfloat16* __restrict__ Kgl,
               const __nv_bfloat16* __restrict__ Vgh, const __nv_bfloat16* __restrict__ Vgl,
               const float* __restrict__ bias,
               __nv_bfloat16* __restrict__ Oh, __nv_bfloat16* __restrict__ Ol)
{
    __shared__ __align__(1024) char sm[49152];
    const uint32_t sb = smem_u32(sm);
    int bh = blockIdx.x, b = bh >> 4, h = bh & 15;
    int q0 = blockIdx.y * 64;
    int tid = threadIdx.x, w = tid >> 5, lane = tid & 31;

    // load Q tiles (hi/lo)
    {
        const __nv_bfloat16* qgh = Qh + ((size_t)(b * SEQ + q0)) * HID + h * 64;
        const __nv_bfloat16* qgl = Ql + ((size_t)(b * SEQ + q0)) * HID + h * 64;
        #pragma unroll
        for (int i = 0; i < 4; i++) {
            int idx = tid + i * 128;
            int r = idx >> 3, g = idx & 7;
            uint32_t d = sb + r * 128 + ((g ^ (r & 7)) << 4);
            CP_ASYNC16(d, qgh + (size_t)r * HID + g * 8);
            CP_ASYNC16(d + 8192, qgl + (size_t)r * HID + g * 8);
        }
    }
    auto issueKV = [&](int k0) {
        const __nv_bfloat16* kgh = Kgh + ((size_t)(b * SEQ + k0)) * HID + h * 64;
        const __nv_bfloat16* kgl = Kgl + ((size_t)(b * SEQ + k0)) * HID + h * 64;
        const __nv_bfloat16* vgh = Vgh + ((size_t)(b * SEQ + k0)) * HID + h * 64;
        const __nv_bfloat16* vgl = Vgl + ((size_t)(b * SEQ + k0)) * HID + h * 64;
        #pragma unroll
        for (int i = 0; i < 4; i++) {
            int idx = tid + i * 128;
            int r = idx >> 3, g = idx & 7;
            uint32_t d = sb + r * 128 + ((g ^ (r & 7)) << 4);
            size_t go = (size_t)r * HID + g * 8;
            CP_ASYNC16(d + 16384, kgh + go);
            CP_ASYNC16(d + 24576, kgl + go);
            CP_ASYNC16(d + 32768, vgh + go);
            CP_ASYNC16(d + 40960, vgl + go);
        }
        CP_COMMIT();
    };

    issueKV(0);

    int wq0 = w * 16;
    int rl = lane & 15, gt = lane >> 4, xa = rl & 7;
    int qr = lane >> 2, qc = lane & 3;

    float oacc[8][4] = {};
    float mrow0 = -1e30f, mrow1 = -1e30f, lrow0 = 0.f, lrow1 = 0.f;

    for (int kt = 0; kt < 16; kt++) {
        CP_WAIT0();
        __syncthreads();

        // ---- S = Q @ K^T (split bf16) ----
        float sacc[8][4] = {};
        #pragma unroll
        for (int s = 0; s < 4; s++) {
            uint32_t qa = sb + (wq0 + rl) * 128 + (((s * 2 + gt) ^ xa) << 4);
            uint32_t Qhf[4], Qlf[4];
            LDX4(Qhf, qa);
            LDX4(Qlf, qa + 8192);
            #pragma unroll
            for (int ni = 0; ni < 4; ni++) {
                uint32_t ka = sb + 16384 + (ni * 16 + rl) * 128 + (((s * 2 + gt) ^ xa) << 4);
                uint32_t Kh4[4], Kl4[4];
                LDX4(Kh4, ka);
                LDX4(Kl4, ka + 8192);
                uint32_t f0h[2] = {Kh4[0], Kh4[2]}, f1h[2] = {Kh4[1], Kh4[3]};
                uint32_t f0l[2] = {Kl4[0], Kl4[2]}, f1l[2] = {Kl4[1], Kl4[3]};
                mma_bf16(sacc[ni * 2],     Qhf, f0h);
                mma_bf16(sacc[ni * 2],     Qhf, f0l);
                mma_bf16(sacc[ni * 2],     Qlf, f0h);
                mma_bf16(sacc[ni * 2 + 1], Qhf, f1h);
                mma_bf16(sacc[ni * 2 + 1], Qhf, f1l);
                mma_bf16(sacc[ni * 2 + 1], Qlf, f1h);
            }
        }

        // ---- bias + online softmax (registers) ----
        {
            const float* bb = bias + ((size_t)bh * SEQ + q0 + wq0 + qr) * SEQ
                            + kt * 64 + qc * 2;
            #pragma unroll
            for (int f = 0; f < 8; f++) {
                float2 b0 = *(const float2*)(bb + f * 8);
                float2 b1 = *(const float2*)(bb + 8 * SEQ + f * 8);
                sacc[f][0] += b0.x; sacc[f][1] += b0.y;
                sacc[f][2] += b1.x; sacc[f][3] += b1.y;
            }
            float mx0 = -1e30f, mx1 = -1e30f;
            #pragma unroll
            for (int f = 0; f < 8; f++) {
                mx0 = fmaxf(mx0, fmaxf(sacc[f][0], sacc[f][1]));
                mx1 = fmaxf(mx1, fmaxf(sacc[f][2], sacc[f][3]));
            }
            mx0 = fmaxf(mx0, __shfl_xor_sync(0xffffffffu, mx0, 1));
            mx0 = fmaxf(mx0, __shfl_xor_sync(0xffffffffu, mx0, 2));
            mx1 = fmaxf(mx1, __shfl_xor_sync(0xffffffffu, mx1, 1));
            mx1 = fmaxf(mx1, __shfl_xor_sync(0xffffffffu, mx1, 2));
            float mn0 = fmaxf(mrow0, mx0), mn1 = fmaxf(mrow1, mx1);
            float sf0 = __expf(mrow0 - mn0), sf1 = __expf(mrow1 - mn1);
            float sum0 = 0.f, sum1 = 0.f;
            #pragma unroll
            for (int f = 0; f < 8; f++) {
                float p0 = __expf(sacc[f][0] - mn0);
                float p1 = __expf(sacc[f][1] - mn0);
                float p2 = __expf(sacc[f][2] - mn1);
                float p3 = __expf(sacc[f][3] - mn1);
                sacc[f][0] = p0; sacc[f][1] = p1; sacc[f][2] = p2; sacc[f][3] = p3;
                sum0 += p0 + p1; sum1 += p2 + p3;
            }
            sum0 += __shfl_xor_sync(0xffffffffu, sum0, 1);
            sum0 += __shfl_xor_sync(0xffffffffu, sum0, 2);
            sum1 += __shfl_xor_sync(0xffffffffu, sum1, 1);
            sum1 += __shfl_xor_sync(0xffffffffu, sum1, 2);
            mrow0 = mn0; mrow1 = mn1;
            lrow0 = lrow0 * sf0 + sum0;
            lrow1 = lrow1 * sf1 + sum1;
            #pragma unroll
            for (int f = 0; f < 8; f++) {
                oacc[f][0] *= sf0; oacc[f][1] *= sf0;
                oacc[f][2] *= sf1; oacc[f][3] *= sf1;
            }
        }

        // ---- O += P @ V (split bf16) ----
        #pragma unroll
        for (int kb = 0; kb < 4; kb++) {
            uint32_t pah[4], pal[4];
            pack2(sacc[2*kb][0],   sacc[2*kb][1],   pah[0], pal[0]);
            pack2(sacc[2*kb][2],   sacc[2*kb][3],   pah[1], pal[1]);
            pack2(sacc[2*kb+1][0], sacc[2*kb+1][1], pah[2], pal[2]);
            pack2(sacc[2*kb+1][2], sacc[2*kb+1][3], pah[3], pal[3]);
            #pragma unroll
            for (int di = 0; di < 4; di++) {
                uint32_t va = sb + 32768 + (kb * 16 + rl) * 128
                            + (((di * 2 + gt) ^ xa) << 4);
                uint32_t Vh4[4], Vl4[4];
                LDX4T(Vh4, va);
                LDX4T(Vl4, va + 8192);
                #pragma unroll
                for (int nj = 0; nj < 2; nj++) {
                    float* d = oacc[di * 2 + nj];
                    mma_bf16(d, pah, Vh4 + nj * 2);
                    mma_bf16(d, pah, Vl4 + nj * 2);
                    mma_bf16(d, pal, Vh4 + nj * 2);
                }
            }
        }
        __syncthreads();
        if (kt + 1 < 16) issueKV((kt + 1) * 64);
    }

    // ---- epilogue: normalize, split, store ----
    float inv0 = 1.f / lrow0, inv1 = 1.f / lrow1;
    size_t row0 = (size_t)(b * SEQ + q0 + wq0 + qr);
    #pragma unroll
    for (int f = 0; f < 8; f++) {
        int col = h * 64 + f * 8 + qc * 2;
        uint32_t H, L;
        pack2(oacc[f][0] * inv0, oacc[f][1] * inv0, H, L);
        *(uint32_t*)(Oh + row0 * HID + col) = H;
        *(uint32_t*)(Ol + row0 * HID + col) = L;
        pack2(oacc[f][2] * inv1, oacc[f][3] * inv1, H, L);
        *(uint32_t*)(Oh + (row0 + 8) * HID + col) = H;
        *(uint32_t*)(Ol + (row0 + 8) * HID + col) = L;
    }
}

// ---------------- launch ----------------
extern "C" void kernel_launch(void* const* d_in, const int* in_sizes, int n_in,
                              void* d_out, int out_size)
{
    const float* x1 = (const float*)d_in[0];
    const float* x2 = (const float*)d_in[1];
    const float* attn_bias = (const float*)d_in[2];
    const float* ln1_g = (const float*)d_in[3];
    const float* ln1_b = (const float*)d_in[4];
    const float* ln2_g = (const float*)d_in[5];
    const float* ln2_b = (const float*)d_in[6];
    const float* wq = (const float*)d_in[7];
    const float* bq = (const float*)d_in[8];
    const float* wk = (const float*)d_in[9];
    const float* bk = (const float*)d_in[10];
    const float* wv = (const float*)d_in[11];
    const float* bv = (const float*)d_in[12];
    const float* wo = (const float*)d_in[13];
    const float* bo = (const float*)d_in[14];
    const float* lnf_g = (const float*)d_in[15];
    const float* lnf_b = (const float*)d_in[16];
    const float* w1 = (const float*)d_in[17];
    const float* b1 = (const float*)d_in[18];
    const float* w2 = (const float*)d_in[19];
    const float* b2 = (const float*)d_in[20];
    float* out = (float*)d_out;

    float* x;
    __nv_bfloat16 *y1h,*y1l,*y2h,*y2l,*qh,*ql,*kh,*kl,*vh,*vl,*oh,*ol,*xlh,*xll,*fh,*fl;
    __nv_bfloat16 *wqh,*wql,*wkh,*wkl,*wvh,*wvl,*woh,*wol,*w1h,*w1l,*w2h,*w2l;
    cudaGetSymbolAddress((void**)&x, g_x);
    cudaGetSymbolAddress((void**)&y1h, g_y1h); cudaGetSymbolAddress((void**)&y1l, g_y1l);
    cudaGetSymbolAddress((void**)&y2h, g_y2h); cudaGetSymbolAddress((void**)&y2l, g_y2l);
    cudaGetSymbolAddress((void**)&qh, g_qh);   cudaGetSymbolAddress((void**)&ql, g_ql);
    cudaGetSymbolAddress((void**)&kh, g_kh);   cudaGetSymbolAddress((void**)&kl, g_kl);
    cudaGetSymbolAddress((void**)&vh, g_vh);   cudaGetSymbolAddress((void**)&vl, g_vl);
    cudaGetSymbolAddress((void**)&oh, g_oh);   cudaGetSymbolAddress((void**)&ol, g_ol);
    cudaGetSymbolAddress((void**)&xlh, g_xlh); cudaGetSymbolAddress((void**)&xll, g_xll);
    cudaGetSymbolAddress((void**)&fh, g_fh);   cudaGetSymbolAddress((void**)&fl, g_fl);
    cudaGetSymbolAddress((void**)&wqh, g_wqh); cudaGetSymbolAddress((void**)&wql, g_wql);
    cudaGetSymbolAddress((void**)&wkh, g_wkh); cudaGetSymbolAddress((void**)&wkl, g_wkl);
    cudaGetSymbolAddress((void**)&wvh, g_wvh); cudaGetSymbolAddress((void**)&wvl, g_wvl);
    cudaGetSymbolAddress((void**)&woh, g_woh); cudaGetSymbolAddress((void**)&wol, g_wol);
    cudaGetSymbolAddress((void**)&w1h, g_w1h); cudaGetSymbolAddress((void**)&w1l, g_w1l);
    cudaGetSymbolAddress((void**)&w2h, g_w2h); cudaGetSymbolAddress((void**)&w2l, g_w2l);

    cudaFuncSetAttribute(mma_gemm, cudaFuncAttributeMaxDynamicSharedMemorySize, GEMM_DSM);

    wsplit<<<HID * HID / 2048, 256>>>(wq, wqh, wql, HID * HID);
    wsplit<<<HID * HID / 2048, 256>>>(wk, wkh, wkl, HID * HID);
    wsplit<<<HID * HID / 2048, 256>>>(wv, wvh, wvl, HID * HID);
    wsplit<<<HID * HID / 2048, 256>>>(wo, woh, wol, HID * HID);
    wsplit<<<HID * FFDIM / 2048, 256>>>(w1, w1h, w1l, HID * FFDIM);
    wsplit<<<FFDIM * HID / 2048, 256>>>(w2, w2h, w2l, FFDIM * HID);

    ln_split<<<ROWS, 128>>>(x1, ln1_g, ln1_b, y1h, y1l);
    ln_split<<<ROWS, 128>>>(x2, ln2_g, ln2_b, y2h, y2l);

    dim3 gP(HID / 128, ROWS / 128);  // (8, 32)
    mma_gemm<<<gP, 256, GEMM_DSM>>>(y2h, y2l, wqh, wql, bq, nullptr, nullptr, qh, ql,
                                    ROWS, HID, HID, M_SPLIT, 0.125f);
    mma_gemm<<<gP, 256, GEMM_DSM>>>(y1h, y1l, wkh, wkl, bk, nullptr, nullptr, kh, kl,
                                    ROWS, HID, HID, M_SPLIT, 1.f);
    mma_gemm<<<gP, 256, GEMM_DSM>>>(y1h, y1l, wvh, wvl, bv, nullptr, nullptr, vh, vl,
                                    ROWS, HID, HID, M_SPLIT, 1.f);

    flash_mma<<<dim3(64, 16), 128>>>(qh, ql, kh, kl, vh, vl, attn_bias, oh, ol);

    mma_gemm<<<gP, 256, GEMM_DSM>>>(oh, ol, woh, wol, bo, x2, x, nullptr, nullptr,
                                    ROWS, HID, HID, M_RES, 1.f);

    ln_split<<<ROWS, 128>>>(x, lnf_g, lnf_b, xlh, xll);

    mma_gemm<<<dim3(FFDIM / 128, ROWS / 128), 256, GEMM_DSM>>>(
        xlh, xll, w1h, w1l, b1, nullptr, nullptr, fh, fl, ROWS, FFDIM, HID, M_GELU, 1.f);
    mma_gemm<<<gP, 256, GEMM_DSM>>>(fh, fl, w2h, w2l, b2, x, out, nullptr, nullptr,
                                    ROWS, HID, FFDIM, M_RES, 1.f);
}